// round 3
// baseline (speedup 1.0000x reference)
#include <cuda_runtime.h>
#include <cuda_bf16.h>
#include <cstdint>

#define BATCH 8
#define NN    2048
#define DD    128
#define NEG_INF_F (-9e15f)
#define LRELU_ALPHA 0.2f

// ---------------- device scratch (no allocation allowed) ----------------
__device__ float g_h[BATCH * NN * DD];
__device__ float g_x[BATCH * NN * DD];
__device__ float g_s1[BATCH * NN];
__device__ float g_s2[BATCH * NN];

// ---------------- packed f32x2 helpers ----------------
__device__ __forceinline__ unsigned long long pack2(float v) {
    unsigned long long r;
    asm("mov.b64 %0, {%1, %1};" : "=l"(r) : "f"(v));
    return r;
}
__device__ __forceinline__ void fma2(unsigned long long& d,
                                     unsigned long long a,
                                     unsigned long long b) {
    asm("fma.rn.f32x2 %0, %1, %2, %0;" : "+l"(d) : "l"(a), "l"(b));
}

// ---------------- Kernel A: h = relu(x @ W + b) ----------------
// grid (N/64, B), 128 threads. 64x128 tile per block, 8x8 per thread, BK=16.
__global__ __launch_bounds__(128) void k_gemm_relu(
    const float* __restrict__ X, const float* __restrict__ W,
    const float* __restrict__ bias, float* __restrict__ H)
{
    __shared__ float sA[16][65];   // transposed x tile [k][m], padded
    __shared__ float sB[16][128];  // W tile [k][n]
    const int b    = blockIdx.y;
    const int row0 = blockIdx.x * 64;
    const int tid  = threadIdx.x;
    const int tm   = (tid >> 4) << 3;   // 0..56
    const int tn   = (tid & 15) << 3;   // 0..120
    const float* Xb = X + ((size_t)b * NN + row0) * DD;

    float acc[8][8];
#pragma unroll
    for (int i = 0; i < 8; i++)
#pragma unroll
        for (int j = 0; j < 8; j++) acc[i][j] = 0.f;

    for (int k0 = 0; k0 < DD; k0 += 16) {
#pragma unroll
        for (int i = 0; i < 2; i++) {
            int idx = tid + i * 128;          // 0..255 float4 slots
            int m   = idx >> 2;               // 0..63
            int kk  = (idx & 3) << 2;         // 0,4,8,12
            float4 v = *(const float4*)(Xb + (size_t)m * DD + k0 + kk);
            sA[kk + 0][m] = v.x; sA[kk + 1][m] = v.y;
            sA[kk + 2][m] = v.z; sA[kk + 3][m] = v.w;
        }
#pragma unroll
        for (int i = 0; i < 4; i++) {
            int idx = tid + i * 128;          // 0..511 float4 slots
            int kk  = idx >> 5;               // 0..15
            int n4  = (idx & 31) << 2;
            *(float4*)&sB[kk][n4] = *(const float4*)(W + (size_t)(k0 + kk) * DD + n4);
        }
        __syncthreads();
#pragma unroll
        for (int kk = 0; kk < 16; kk++) {
            float a[8], bb[8];
#pragma unroll
            for (int i = 0; i < 8; i++) a[i]  = sA[kk][tm + i];
#pragma unroll
            for (int j = 0; j < 8; j++) bb[j] = sB[kk][tn + j];
#pragma unroll
            for (int i = 0; i < 8; i++)
#pragma unroll
                for (int j = 0; j < 8; j++)
                    acc[i][j] = fmaf(a[i], bb[j], acc[i][j]);
        }
        __syncthreads();
    }

    float* Hb = H + ((size_t)b * NN + row0) * DD;
#pragma unroll
    for (int i = 0; i < 8; i++) {
        float4 o0, o1;
        o0.x = acc[i][0] + bias[tn + 0]; o0.y = acc[i][1] + bias[tn + 1];
        o0.z = acc[i][2] + bias[tn + 2]; o0.w = acc[i][3] + bias[tn + 3];
        o1.x = acc[i][4] + bias[tn + 4]; o1.y = acc[i][5] + bias[tn + 5];
        o1.z = acc[i][6] + bias[tn + 6]; o1.w = acc[i][7] + bias[tn + 7];
        o0.x = fmaxf(o0.x, 0.f); o0.y = fmaxf(o0.y, 0.f);
        o0.z = fmaxf(o0.z, 0.f); o0.w = fmaxf(o0.w, 0.f);
        o1.x = fmaxf(o1.x, 0.f); o1.y = fmaxf(o1.y, 0.f);
        o1.z = fmaxf(o1.z, 0.f); o1.w = fmaxf(o1.w, 0.f);
        *(float4*)(Hb + (size_t)(tm + i) * DD + tn)     = o0;
        *(float4*)(Hb + (size_t)(tm + i) * DD + tn + 4) = o1;
    }
}

// ---------------- Kernel S: s1 = h@a1, s2 = h@a2 ----------------
// one warp per row, 8 warps/block, grid = B*N/8 = 2048
__global__ __launch_bounds__(256) void k_scores(
    const float* __restrict__ H, const float* __restrict__ a1,
    const float* __restrict__ a2, float* __restrict__ s1, float* __restrict__ s2)
{
    const int warp = threadIdx.x >> 5;
    const int lane = threadIdx.x & 31;
    const size_t row = (size_t)blockIdx.x * 8 + warp;  // 0..16383
    const float* hr = H + row * DD;
    float4 h4 = *(const float4*)(hr + lane * 4);
    float4 A  = *(const float4*)(a1 + lane * 4);
    float4 Bv = *(const float4*)(a2 + lane * 4);
    float d1 = h4.x * A.x + h4.y * A.y + h4.z * A.z + h4.w * A.w;
    float d2 = h4.x * Bv.x + h4.y * Bv.y + h4.z * Bv.z + h4.w * Bv.w;
#pragma unroll
    for (int o = 16; o > 0; o >>= 1) {
        d1 += __shfl_xor_sync(0xffffffffu, d1, o);
        d2 += __shfl_xor_sync(0xffffffffu, d2, o);
    }
    if (lane == 0) { s1[row] = d1; s2[row] = d2; }
}

// ---------------- Kernel B: masked softmax + aggregation + residual ----------------
// grid (N/8, B), 256 threads (8 warps), TI=8 rows per block, TJ=64 j-tile.
// smem: p[8][2048] (64KB) + h tile / reduce buffer [64][128] (32KB) = 96KB dynamic.
__global__ __launch_bounds__(256, 2) void k_attn(
    const float* __restrict__ H, const int* __restrict__ ADJ,
    const float* __restrict__ S1, const float* __restrict__ S2,
    const float* __restrict__ Xin, float* __restrict__ Xout)
{
    constexpr int TI = 8, TJ = 64;
    extern __shared__ float smem[];
    float* sp = smem;                 // [TI][NN]
    float* sh = smem + TI * NN;       // [TJ][DD], reused as reduce buffer
    __shared__ float s_l[TI];

    const int b   = blockIdx.y;
    const int i0  = blockIdx.x * TI;
    const int tid = threadIdx.x;
    const int warp = tid >> 5;
    const int lane = tid & 31;

    // ---- Phase 1: warp w handles row i0+w; scores -> p in smem, softmax stats
    {
        const int i = i0 + warp;
        const int* __restrict__ adjrow = ADJ + ((size_t)b * NN + i) * NN;
        const float* __restrict__ s2row = S2 + (size_t)b * NN;
        const float s1v = S1[(size_t)b * NN + i];
        float* sprow = sp + warp * NN;
        float m = NEG_INF_F;
        for (int j = lane; j < NN; j += 32) {
            float e = s1v + __ldg(&s2row[j]);
            e = (e > 0.f) ? e : LRELU_ALPHA * e;
            e = (adjrow[j] != 0) ? e : NEG_INF_F;
            sprow[j] = e;
            m = fmaxf(m, e);
        }
#pragma unroll
        for (int o = 16; o > 0; o >>= 1)
            m = fmaxf(m, __shfl_xor_sync(0xffffffffu, m, o));
        float l = 0.f;
        for (int j = lane; j < NN; j += 32) {
            float p = __expf(sprow[j] - m);
            sprow[j] = p;
            l += p;
        }
#pragma unroll
        for (int o = 16; o > 0; o >>= 1)
            l += __shfl_xor_sync(0xffffffffu, l, o);
        if (lane == 0) s_l[warp] = l;
    }
    __syncthreads();

    // ---- Phase 2: acc += p_j * h_j. Each warp covers all 8 rows x 128 d for
    // its own jj slice (8 j per tile). Thread: 4 rows (by half-warp) x 8 d.
    const int sub  = lane >> 4;          // 0: rows 0-3, 1: rows 4-7
    const int dcol = (lane & 15) << 3;   // d base, 8 wide

    unsigned long long acc[4][4];
#pragma unroll
    for (int r = 0; r < 4; r++)
#pragma unroll
        for (int k = 0; k < 4; k++) acc[r][k] = 0ull;

    for (int j0 = 0; j0 < NN; j0 += TJ) {
        __syncthreads();
        {
            const float4* hsrc = (const float4*)(H + ((size_t)b * NN + j0) * DD);
            float4* hdst = (float4*)sh;
#pragma unroll
            for (int t = 0; t < (TJ * DD / 4) / 256; t++)
                hdst[tid + t * 256] = hsrc[tid + t * 256];
        }
        __syncthreads();

        const float* sprow0 = sp + (sub * 4) * NN + j0 + (warp << 3);
        const float* shbase = sh + (warp << 3) * DD + dcol;
#pragma unroll
        for (int u = 0; u < 8; u += 2) {
            ulonglong2 h0a = *(const ulonglong2*)(shbase + (size_t)u * DD);
            ulonglong2 h0b = *(const ulonglong2*)(shbase + (size_t)u * DD + 4);
            ulonglong2 h1a = *(const ulonglong2*)(shbase + (size_t)(u + 1) * DD);
            ulonglong2 h1b = *(const ulonglong2*)(shbase + (size_t)(u + 1) * DD + 4);
#pragma unroll
            for (int r = 0; r < 4; r++) {
                float2 w = *(const float2*)(sprow0 + (size_t)r * NN + u);
                unsigned long long wx = pack2(w.x);
                unsigned long long wy = pack2(w.y);
                fma2(acc[r][0], wx, h0a.x); fma2(acc[r][1], wx, h0a.y);
                fma2(acc[r][2], wx, h0b.x); fma2(acc[r][3], wx, h0b.y);
                fma2(acc[r][0], wy, h1a.x); fma2(acc[r][1], wy, h1a.y);
                fma2(acc[r][2], wy, h1b.x); fma2(acc[r][3], wy, h1b.y);
            }
        }
    }

    // ---- cross-warp reduction of partials (reuse sh: 8 warps x 8 rows x 128 d)
    __syncthreads();
#pragma unroll
    for (int r = 0; r < 4; r++)
#pragma unroll
        for (int k = 0; k < 4; k++)
            *(unsigned long long*)(sh + (size_t)warp * 1024 +
                                   (size_t)(sub * 4 + r) * DD + dcol + k * 2) = acc[r][k];
    __syncthreads();
    {
        const int row = tid >> 5;              // 0..7
        const int d4  = (lane) << 2;           // 0..124
        float4 sum = make_float4(0.f, 0.f, 0.f, 0.f);
#pragma unroll
        for (int w = 0; w < 8; w++) {
            float4 v = *(const float4*)(sh + (size_t)w * 1024 + (size_t)row * DD + d4);
            sum.x += v.x; sum.y += v.y; sum.z += v.z; sum.w += v.w;
        }
        const float inv = 1.0f / s_l[row];
        const size_t off = ((size_t)b * NN + i0 + row) * DD + d4;
        float4 xv = *(const float4*)(Xin + off);
        float4 o;
        o.x = xv.x + sum.x * inv; o.y = xv.y + sum.y * inv;
        o.z = xv.z + sum.z * inv; o.w = xv.w + sum.w * inv;
        *(float4*)(Xout + off) = o;
    }
}

// ---------------- host launcher ----------------
extern "C" void kernel_launch(void* const* d_in, const int* in_sizes, int n_in,
                              void* d_out, int out_size)
{
    (void)in_sizes; (void)n_in; (void)out_size;
    const float* x   = (const float*)d_in[0];
    const int*   adj = (const int*)d_in[1];
    const float* Wg  = (const float*)d_in[2];
    const float* bg  = (const float*)d_in[3];
    const float* aa  = (const float*)d_in[4];
    float* out = (float*)d_out;

    float *h, *xbuf, *s1, *s2;
    cudaGetSymbolAddress((void**)&h,    g_h);
    cudaGetSymbolAddress((void**)&xbuf, g_x);
    cudaGetSymbolAddress((void**)&s1,   g_s1);
    cudaGetSymbolAddress((void**)&s2,   g_s2);

    const int smemB = (8 * NN + 64 * DD) * (int)sizeof(float);  // 96KB
    cudaFuncSetAttribute(k_attn, cudaFuncAttributeMaxDynamicSharedMemorySize, smemB);

    for (int l = 0; l < 3; l++) {
        const float* xin  = (l == 0) ? x : xbuf;
        float*       xout = (l == 2) ? out : xbuf;
        k_gemm_relu<<<dim3(NN / 64, BATCH), 128>>>(xin, Wg + (size_t)l * DD * DD,
                                                   bg + (size_t)l * DD, h);
        k_scores<<<BATCH * NN / 8, 256>>>(h, aa + (size_t)l * 2 * DD,
                                          aa + (size_t)l * 2 * DD + DD, s1, s2);
        k_attn<<<dim3(NN / 8, BATCH), 256, smemB>>>(h, adj, s1, s2, xin, xout);
    }
}

// round 6
// speedup vs baseline: 3.7149x; 3.7149x over previous
#include <cuda_runtime.h>
#include <cuda_bf16.h>
#include <cstdint>

#define BATCH 8
#define NN    2048
#define DD    128
#define NEG_INF_F (-9e15f)
#define LRELU_ALPHA 0.2f

// ---------------- device scratch (no allocation allowed) ----------------
__device__ float g_h[BATCH * NN * DD];
__device__ float g_x[BATCH * NN * DD];
__device__ __nv_bfloat16 g_hT[BATCH * DD * NN];            // transposed h, bf16 (B operand)
__device__ __nv_bfloat16 g_p[(size_t)BATCH * NN * NN];     // unnormalized softmax weights
__device__ float g_s1[BATCH * NN];
__device__ float g_s2[BATCH * NN];
__device__ float g_l[BATCH * NN];                          // softmax denominators

// ---------------- helpers ----------------
__device__ __forceinline__ uint32_t smem_u32(const void* p) {
    uint32_t a;
    asm("{ .reg .u64 t; cvta.to.shared.u64 t, %1; cvt.u32.u64 %0, t; }"
        : "=r"(a) : "l"(p));
    return a;
}
__device__ __forceinline__ void cpasync16(uint32_t dst, const void* src) {
    asm volatile("cp.async.cg.shared.global [%0], [%1], 16;"
                 :: "r"(dst), "l"(src) : "memory");
}
__device__ __forceinline__ void cp_commit() {
    asm volatile("cp.async.commit_group;" ::: "memory");
}
__device__ __forceinline__ void ldm4(uint32_t* r, uint32_t addr) {
    asm volatile("ldmatrix.sync.aligned.m8n8.x4.shared.b16 {%0,%1,%2,%3}, [%4];"
                 : "=r"(r[0]), "=r"(r[1]), "=r"(r[2]), "=r"(r[3]) : "r"(addr));
}
__device__ __forceinline__ void mma_bf16(float* c, const uint32_t* a,
                                         uint32_t b0, uint32_t b1) {
    asm volatile(
        "mma.sync.aligned.m16n8k16.row.col.f32.bf16.bf16.f32 "
        "{%0,%1,%2,%3}, {%4,%5,%6,%7}, {%8,%9}, {%0,%1,%2,%3};"
        : "+f"(c[0]), "+f"(c[1]), "+f"(c[2]), "+f"(c[3])
        : "r"(a[0]), "r"(a[1]), "r"(a[2]), "r"(a[3]), "r"(b0), "r"(b1));
}
// swizzled byte offset of 16B chunk c (0..3) of row r in a [rows][32 bf16] tile
__device__ __forceinline__ uint32_t swz(int r, int c) {
    return (uint32_t)(r * 64 + (((c) ^ ((r >> 1) & 3)) << 4));
}

// ---------------- Kernel A: h = relu(x @ W + b), fp32 H + bf16 H^T ----------------
__global__ __launch_bounds__(128) void k_gemm_relu(
    const float* __restrict__ X, const float* __restrict__ W,
    const float* __restrict__ bias, float* __restrict__ H,
    __nv_bfloat16* __restrict__ HT)
{
    __shared__ float sA[16][65];
    __shared__ float sB[16][128];
    const int b    = blockIdx.y;
    const int row0 = blockIdx.x * 64;
    const int tid  = threadIdx.x;
    const int tm   = (tid >> 4) << 3;
    const int tn   = (tid & 15) << 3;
    const float* Xb = X + ((size_t)b * NN + row0) * DD;

    float acc[8][8];
#pragma unroll
    for (int i = 0; i < 8; i++)
#pragma unroll
        for (int j = 0; j < 8; j++) acc[i][j] = 0.f;

    for (int k0 = 0; k0 < DD; k0 += 16) {
#pragma unroll
        for (int i = 0; i < 2; i++) {
            int idx = tid + i * 128;
            int m   = idx >> 2;
            int kk  = (idx & 3) << 2;
            float4 v = *(const float4*)(Xb + (size_t)m * DD + k0 + kk);
            sA[kk + 0][m] = v.x; sA[kk + 1][m] = v.y;
            sA[kk + 2][m] = v.z; sA[kk + 3][m] = v.w;
        }
#pragma unroll
        for (int i = 0; i < 4; i++) {
            int idx = tid + i * 128;
            int kk  = idx >> 5;
            int n4  = (idx & 31) << 2;
            *(float4*)&sB[kk][n4] = *(const float4*)(W + (size_t)(k0 + kk) * DD + n4);
        }
        __syncthreads();
#pragma unroll
        for (int kk = 0; kk < 16; kk++) {
            float a[8], bb[8];
#pragma unroll
            for (int i = 0; i < 8; i++) a[i]  = sA[kk][tm + i];
#pragma unroll
            for (int j = 0; j < 8; j++) bb[j] = sB[kk][tn + j];
#pragma unroll
            for (int i = 0; i < 8; i++)
#pragma unroll
                for (int j = 0; j < 8; j++)
                    acc[i][j] = fmaf(a[i], bb[j], acc[i][j]);
        }
        __syncthreads();
    }

    float bi[8];
#pragma unroll
    for (int j = 0; j < 8; j++) bi[j] = bias[tn + j];
#pragma unroll
    for (int i = 0; i < 8; i++)
#pragma unroll
        for (int j = 0; j < 8; j++)
            acc[i][j] = fmaxf(acc[i][j] + bi[j], 0.f);

    float* Hb = H + ((size_t)b * NN + row0) * DD;
#pragma unroll
    for (int i = 0; i < 8; i++) {
        float4 o0, o1;
        o0.x = acc[i][0]; o0.y = acc[i][1]; o0.z = acc[i][2]; o0.w = acc[i][3];
        o1.x = acc[i][4]; o1.y = acc[i][5]; o1.z = acc[i][6]; o1.w = acc[i][7];
        *(float4*)(Hb + (size_t)(tm + i) * DD + tn)     = o0;
        *(float4*)(Hb + (size_t)(tm + i) * DD + tn + 4) = o1;
    }
    // bf16 transposed store: HT[b][d][j]
#pragma unroll
    for (int j = 0; j < 8; j++) {
        union { __nv_bfloat162 h2[4]; uint4 u; } cv;
        cv.h2[0] = __float22bfloat162_rn(make_float2(acc[0][j], acc[1][j]));
        cv.h2[1] = __float22bfloat162_rn(make_float2(acc[2][j], acc[3][j]));
        cv.h2[2] = __float22bfloat162_rn(make_float2(acc[4][j], acc[5][j]));
        cv.h2[3] = __float22bfloat162_rn(make_float2(acc[6][j], acc[7][j]));
        *(uint4*)(HT + ((size_t)b * DD + tn + j) * NN + row0 + tm) = cv.u;
    }
}

// ---------------- Kernel S: s1 = h@a1, s2 = h@a2 ----------------
__global__ __launch_bounds__(256) void k_scores(
    const float* __restrict__ H, const float* __restrict__ a1,
    const float* __restrict__ a2, float* __restrict__ s1, float* __restrict__ s2)
{
    const int warp = threadIdx.x >> 5;
    const int lane = threadIdx.x & 31;
    const size_t row = (size_t)blockIdx.x * 8 + warp;
    const float* hr = H + row * DD;
    float4 h4 = *(const float4*)(hr + lane * 4);
    float4 A  = *(const float4*)(a1 + lane * 4);
    float4 Bv = *(const float4*)(a2 + lane * 4);
    float d1 = h4.x * A.x + h4.y * A.y + h4.z * A.z + h4.w * A.w;
    float d2 = h4.x * Bv.x + h4.y * Bv.y + h4.z * Bv.z + h4.w * Bv.w;
#pragma unroll
    for (int o = 16; o > 0; o >>= 1) {
        d1 += __shfl_xor_sync(0xffffffffu, d1, o);
        d2 += __shfl_xor_sync(0xffffffffu, d2, o);
    }
    if (lane == 0) { s1[row] = d1; s2[row] = d2; }
}

// ---------------- Kernel P: masked softmax weights -> bf16, row sums ----------------
__global__ __launch_bounds__(256) void k_soft(
    const int* __restrict__ ADJ, const float* __restrict__ S1,
    const float* __restrict__ S2, __nv_bfloat16* __restrict__ Pout,
    float* __restrict__ Lout)
{
    extern __shared__ float sp[];
    const int b    = blockIdx.y;
    const int warp = threadIdx.x >> 5;
    const int lane = threadIdx.x & 31;
    const int i    = blockIdx.x * 8 + warp;

    const int* __restrict__ adjrow = ADJ + ((size_t)b * NN + i) * NN;
    const float* __restrict__ s2row = S2 + (size_t)b * NN;
    const float s1v = S1[(size_t)b * NN + i];
    float* sprow = sp + warp * NN;

    float m = NEG_INF_F;
    for (int j = lane; j < NN; j += 32) {
        float e = s1v + __ldg(&s2row[j]);
        e = (e > 0.f) ? e : LRELU_ALPHA * e;
        e = (adjrow[j] != 0) ? e : NEG_INF_F;
        sprow[j] = e;
        m = fmaxf(m, e);
    }
#pragma unroll
    for (int o = 16; o > 0; o >>= 1)
        m = fmaxf(m, __shfl_xor_sync(0xffffffffu, m, o));

    float l = 0.f;
    __nv_bfloat162* outp = (__nv_bfloat162*)(Pout + ((size_t)b * NN + i) * NN);
    for (int j2 = lane; j2 < NN / 2; j2 += 32) {
        float2 e2 = *(const float2*)&sprow[2 * j2];
        float p0 = __expf(e2.x - m);
        float p1 = __expf(e2.y - m);
        l += p0 + p1;
        outp[j2] = __float22bfloat162_rn(make_float2(p0, p1));
    }
#pragma unroll
    for (int o = 16; o > 0; o >>= 1)
        l += __shfl_xor_sync(0xffffffffu, l, o);
    if (lane == 0) Lout[(size_t)b * NN + i] = l;
}

// ---------------- Kernel M: out = x + (P @ H) / l  via mma.sync bf16 ----------------
// grid (N/128, B), 256 threads (8 warps, 4x2). Block tile 128x128, K-chunks of 32,
// double-buffered cp.async. Warp tile 32x64 = 2x8 m16n8k16.
__global__ __launch_bounds__(256) void k_mma(
    const __nv_bfloat16* __restrict__ P, const __nv_bfloat16* __restrict__ HT,
    const float* __restrict__ L, const float* __restrict__ Xin,
    float* __restrict__ Xout)
{
    __shared__ __align__(16) char sm[2][2][8192];   // [buf][A/B][128 rows x 64B]
    const int b    = blockIdx.y;
    const int i0   = blockIdx.x * 128;
    const int tid  = threadIdx.x;
    const int warp = tid >> 5;
    const int lane = tid & 31;
    const int wm   = warp >> 1;     // 0..3  -> m offset wm*32
    const int wn   = warp & 1;      // 0..1  -> n offset wn*64

    const char* Pb = (const char*)(P + ((size_t)b * NN + i0) * (size_t)NN);
    const char* Hb = (const char*)(HT + (size_t)b * DD * NN);

    // gmem->smem mapping for this thread (2 passes x (1 A + 1 B) 16B chunks)
    const int r_a[2] = { (tid + 0)   >> 2, (tid + 256) >> 2 };
    const int c_a[2] = { tid & 3,          tid & 3 };
    uint32_t swoff[2];
    swoff[0] = swz(r_a[0], c_a[0]);
    swoff[1] = swz(r_a[1], c_a[1]);

    // ldmatrix per-lane offsets (relative to tile base)
    const int lr = lane & 15;       // row within 16-row group
    const int lc = lane >> 4;       // 16B half-selector within k16
    uint32_t offA[2][2], offB[4][2];
#pragma unroll
    for (int mt = 0; mt < 2; mt++)
#pragma unroll
        for (int s = 0; s < 2; s++)
            offA[mt][s] = swz(wm * 32 + mt * 16 + lr, 2 * s + lc);
#pragma unroll
    for (int nt = 0; nt < 4; nt++)
#pragma unroll
        for (int s = 0; s < 2; s++)
            offB[nt][s] = swz(wn * 64 + nt * 16 + lr, 2 * s + lc);

    float acc[2][8][4];
#pragma unroll
    for (int mt = 0; mt < 2; mt++)
#pragma unroll
        for (int nt = 0; nt < 8; nt++)
#pragma unroll
            for (int q = 0; q < 4; q++) acc[mt][nt][q] = 0.f;

    // prefetch chunk 0
    {
        uint32_t sA = smem_u32(&sm[0][0][0]);
        uint32_t sB = sA + 8192;
#pragma unroll
        for (int p = 0; p < 2; p++) {
            cpasync16(sA + swoff[p], Pb + (size_t)r_a[p] * (NN * 2) + c_a[p] * 16);
            cpasync16(sB + swoff[p], Hb + (size_t)r_a[p] * (NN * 2) + c_a[p] * 16);
        }
        cp_commit();
    }

    for (int kc = 0; kc < 64; kc++) {
        if (kc < 63) {
            uint32_t sA = smem_u32(&sm[(kc + 1) & 1][0][0]);
            uint32_t sB = sA + 8192;
            const size_t koff = (size_t)(kc + 1) * 64;
#pragma unroll
            for (int p = 0; p < 2; p++) {
                cpasync16(sA + swoff[p],
                          Pb + (size_t)r_a[p] * (NN * 2) + koff + c_a[p] * 16);
                cpasync16(sB + swoff[p],
                          Hb + (size_t)r_a[p] * (NN * 2) + koff + c_a[p] * 16);
            }
            cp_commit();
            asm volatile("cp.async.wait_group 1;" ::: "memory");
        } else {
            asm volatile("cp.async.wait_group 0;" ::: "memory");
        }
        __syncthreads();

        uint32_t sA = smem_u32(&sm[kc & 1][0][0]);
        uint32_t sB = sA + 8192;
#pragma unroll
        for (int s = 0; s < 2; s++) {
            uint32_t a[2][4];
#pragma unroll
            for (int mt = 0; mt < 2; mt++) ldm4(a[mt], sA + offA[mt][s]);
#pragma unroll
            for (int nt = 0; nt < 4; nt++) {
                uint32_t q[4];
                ldm4(q, sB + offB[nt][s]);
#pragma unroll
                for (int mt = 0; mt < 2; mt++) {
                    mma_bf16(acc[mt][2 * nt + 0], a[mt], q[0], q[2]);
                    mma_bf16(acc[mt][2 * nt + 1], a[mt], q[1], q[3]);
                }
            }
        }
        __syncthreads();
    }

    // epilogue: out = x + acc / l
    const int rbase = i0 + wm * 32 + (lane >> 2);
    const int cbase = wn * 64 + (lane & 3) * 2;
#pragma unroll
    for (int mt = 0; mt < 2; mt++) {
        const int r_lo = rbase + mt * 16;
        const int r_hi = r_lo + 8;
        const float inv_lo = 1.0f / L[(size_t)b * NN + r_lo];
        const float inv_hi = 1.0f / L[(size_t)b * NN + r_hi];
        const float* x_lo = Xin + ((size_t)b * NN + r_lo) * DD;
        const float* x_hi = Xin + ((size_t)b * NN + r_hi) * DD;
        float* o_lo = Xout + ((size_t)b * NN + r_lo) * DD;
        float* o_hi = Xout + ((size_t)b * NN + r_hi) * DD;
#pragma unroll
        for (int nt = 0; nt < 8; nt++) {
            const int cc = cbase + nt * 8;
            float2 xa = *(const float2*)(x_lo + cc);
            float2 xb = *(const float2*)(x_hi + cc);
            float2 oa, ob;
            oa.x = xa.x + acc[mt][nt][0] * inv_lo;
            oa.y = xa.y + acc[mt][nt][1] * inv_lo;
            ob.x = xb.x + acc[mt][nt][2] * inv_hi;
            ob.y = xb.y + acc[mt][nt][3] * inv_hi;
            *(float2*)(o_lo + cc) = oa;
            *(float2*)(o_hi + cc) = ob;
        }
    }
}

// ---------------- host launcher ----------------
extern "C" void kernel_launch(void* const* d_in, const int* in_sizes, int n_in,
                              void* d_out, int out_size)
{
    (void)in_sizes; (void)n_in; (void)out_size;
    const float* x   = (const float*)d_in[0];
    const int*   adj = (const int*)d_in[1];
    const float* Wg  = (const float*)d_in[2];
    const float* bg  = (const float*)d_in[3];
    const float* aa  = (const float*)d_in[4];
    float* out = (float*)d_out;

    float *h, *xbuf, *s1, *s2, *lden;
    __nv_bfloat16 *hT, *p;
    cudaGetSymbolAddress((void**)&h,    g_h);
    cudaGetSymbolAddress((void**)&xbuf, g_x);
    cudaGetSymbolAddress((void**)&s1,   g_s1);
    cudaGetSymbolAddress((void**)&s2,   g_s2);
    cudaGetSymbolAddress((void**)&lden, g_l);
    cudaGetSymbolAddress((void**)&hT,   g_hT);
    cudaGetSymbolAddress((void**)&p,    g_p);

    const int smemSoft = 8 * NN * (int)sizeof(float);          // 64 KB
    cudaFuncSetAttribute(k_soft, cudaFuncAttributeMaxDynamicSharedMemorySize, smemSoft);

    for (int l = 0; l < 3; l++) {
        const float* xin  = (l == 0) ? x : xbuf;
        float*       xout = (l == 2) ? out : xbuf;
        k_gemm_relu<<<dim3(NN / 64, BATCH), 128>>>(xin, Wg + (size_t)l * DD * DD,
                                                   bg + (size_t)l * DD, h, hT);
        k_scores<<<BATCH * NN / 8, 256>>>(h, aa + (size_t)l * 2 * DD,
                                          aa + (size_t)l * 2 * DD + DD, s1, s2);
        k_soft<<<dim3(NN / 8, BATCH), 256, smemSoft>>>(adj, s1, s2, p, lden);
        k_mma<<<dim3(NN / 128, BATCH), 256>>>(p, hT, lden, xin, xout);
    }
}

// round 7
// speedup vs baseline: 5.4768x; 1.4743x over previous
#include <cuda_runtime.h>
#include <cuda_bf16.h>
#include <cstdint>

#define BATCH 8
#define NN    2048
#define DD    128
#define LRELU_ALPHA 0.2f

// ---------------- device scratch (no allocation allowed) ----------------
__device__ __nv_bfloat16 g_hT[BATCH * DD * NN];   // transposed h, bf16 (B operand)
__device__ float g_x[BATCH * NN * DD];            // residual ping-pong
__device__ float g_s1[BATCH * NN];
__device__ float g_s2[BATCH * NN];
__device__ uint32_t g_mask[(size_t)BATCH * NN * (NN / 32)];   // adj bitmask, 4 MB

// ---------------- helpers ----------------
__device__ __forceinline__ uint32_t smem_u32(const void* p) {
    uint32_t a;
    asm("{ .reg .u64 t; cvta.to.shared.u64 t, %1; cvt.u32.u64 %0, t; }"
        : "=r"(a) : "l"(p));
    return a;
}
__device__ __forceinline__ void cpasync16(uint32_t dst, const void* src) {
    asm volatile("cp.async.cg.shared.global [%0], [%1], 16;"
                 :: "r"(dst), "l"(src) : "memory");
}
__device__ __forceinline__ void cp_commit() {
    asm volatile("cp.async.commit_group;" ::: "memory");
}
__device__ __forceinline__ void ldm4(uint32_t* r, uint32_t addr) {
    asm volatile("ldmatrix.sync.aligned.m8n8.x4.shared.b16 {%0,%1,%2,%3}, [%4];"
                 : "=r"(r[0]), "=r"(r[1]), "=r"(r[2]), "=r"(r[3]) : "r"(addr));
}
__device__ __forceinline__ void mma_bf16(float* c, const uint32_t* a,
                                         uint32_t b0, uint32_t b1) {
    asm volatile(
        "mma.sync.aligned.m16n8k16.row.col.f32.bf16.bf16.f32 "
        "{%0,%1,%2,%3}, {%4,%5,%6,%7}, {%8,%9}, {%0,%1,%2,%3};"
        : "+f"(c[0]), "+f"(c[1]), "+f"(c[2]), "+f"(c[3])
        : "r"(a[0]), "r"(a[1]), "r"(a[2]), "r"(a[3]), "r"(b0), "r"(b1));
}
// swizzled byte offset of 16B chunk c (0..3) of row r in a [rows][32 bf16] tile
__device__ __forceinline__ uint32_t swz(int r, int c) {
    return (uint32_t)(r * 64 + (((c) ^ ((r >> 1) & 3)) << 4));
}
// pack two floats to bf16x2 {lo, hi}
__device__ __forceinline__ uint32_t pack_bf16x2(float lo, float hi) {
    uint32_t r;
    asm("cvt.rn.bf16x2.f32 %0, %1, %2;" : "=r"(r) : "f"(hi), "f"(lo));
    return r;
}

// ---------------- Kernel PK: pack adj into bitmask (runs ONCE) ----------------
// grid (NN/8, B), 256 threads, warp per row.
__global__ __launch_bounds__(256) void k_pack(
    const int* __restrict__ ADJ, uint32_t* __restrict__ M)
{
    const int b    = blockIdx.y;
    const int row  = blockIdx.x * 8 + (threadIdx.x >> 5);
    const int lane = threadIdx.x & 31;
    const int* ar = ADJ + ((size_t)b * NN + row) * NN;
    uint32_t* mr  = M + ((size_t)b * NN + row) * (NN / 32);
#pragma unroll 4
    for (int w = 0; w < NN / 32; w++) {
        int v = ar[w * 32 + lane];
        uint32_t bits = __ballot_sync(0xffffffffu, v != 0);
        if (lane == 0) mr[w] = bits;
    }
}

// ---------------- Kernel A: h = relu(x@W+b) -> HT bf16; s1,s2 in epilogue ----------
__global__ __launch_bounds__(128) void k_gemm_relu(
    const float* __restrict__ X, const float* __restrict__ W,
    const float* __restrict__ bias,
    const float* __restrict__ a1, const float* __restrict__ a2,
    __nv_bfloat16* __restrict__ HT,
    float* __restrict__ S1, float* __restrict__ S2)
{
    __shared__ float sA[16][65];
    __shared__ float sB[16][128];
    const int b    = blockIdx.y;
    const int row0 = blockIdx.x * 64;
    const int tid  = threadIdx.x;
    const int tm   = (tid >> 4) << 3;
    const int tn   = (tid & 15) << 3;
    const float* Xb = X + ((size_t)b * NN + row0) * DD;

    float acc[8][8];
#pragma unroll
    for (int i = 0; i < 8; i++)
#pragma unroll
        for (int j = 0; j < 8; j++) acc[i][j] = 0.f;

    for (int k0 = 0; k0 < DD; k0 += 16) {
#pragma unroll
        for (int i = 0; i < 2; i++) {
            int idx = tid + i * 128;
            int m   = idx >> 2;
            int kk  = (idx & 3) << 2;
            float4 v = *(const float4*)(Xb + (size_t)m * DD + k0 + kk);
            sA[kk + 0][m] = v.x; sA[kk + 1][m] = v.y;
            sA[kk + 2][m] = v.z; sA[kk + 3][m] = v.w;
        }
#pragma unroll
        for (int i = 0; i < 4; i++) {
            int idx = tid + i * 128;
            int kk  = idx >> 5;
            int n4  = (idx & 31) << 2;
            *(float4*)&sB[kk][n4] = *(const float4*)(W + (size_t)(k0 + kk) * DD + n4);
        }
        __syncthreads();
#pragma unroll
        for (int kk = 0; kk < 16; kk++) {
            float a[8], bb[8];
#pragma unroll
            for (int i = 0; i < 8; i++) a[i]  = sA[kk][tm + i];
#pragma unroll
            for (int j = 0; j < 8; j++) bb[j] = sB[kk][tn + j];
#pragma unroll
            for (int i = 0; i < 8; i++)
#pragma unroll
                for (int j = 0; j < 8; j++)
                    acc[i][j] = fmaf(a[i], bb[j], acc[i][j]);
        }
        __syncthreads();
    }

    float bi[8];
#pragma unroll
    for (int j = 0; j < 8; j++) bi[j] = bias[tn + j];
#pragma unroll
    for (int i = 0; i < 8; i++)
#pragma unroll
        for (int j = 0; j < 8; j++)
            acc[i][j] = fmaxf(acc[i][j] + bi[j], 0.f);

    // bf16 transposed store: HT[b][d][j]
#pragma unroll
    for (int j = 0; j < 8; j++) {
        union { __nv_bfloat162 h2[4]; uint4 u; } cv;
        cv.h2[0] = __float22bfloat162_rn(make_float2(acc[0][j], acc[1][j]));
        cv.h2[1] = __float22bfloat162_rn(make_float2(acc[2][j], acc[3][j]));
        cv.h2[2] = __float22bfloat162_rn(make_float2(acc[4][j], acc[5][j]));
        cv.h2[3] = __float22bfloat162_rn(make_float2(acc[6][j], acc[7][j]));
        *(uint4*)(HT + ((size_t)b * DD + tn + j) * NN + row0 + tm) = cv.u;
    }

    // s1/s2 epilogue: per-row dot with a1/a2, reduce across 16-thread groups
    float4 A1a = *(const float4*)(a1 + tn);
    float4 A1b = *(const float4*)(a1 + tn + 4);
    float4 A2a = *(const float4*)(a2 + tn);
    float4 A2b = *(const float4*)(a2 + tn + 4);
#pragma unroll
    for (int i = 0; i < 8; i++) {
        float t1 = acc[i][0]*A1a.x + acc[i][1]*A1a.y + acc[i][2]*A1a.z + acc[i][3]*A1a.w
                 + acc[i][4]*A1b.x + acc[i][5]*A1b.y + acc[i][6]*A1b.z + acc[i][7]*A1b.w;
        float t2 = acc[i][0]*A2a.x + acc[i][1]*A2a.y + acc[i][2]*A2a.z + acc[i][3]*A2a.w
                 + acc[i][4]*A2b.x + acc[i][5]*A2b.y + acc[i][6]*A2b.z + acc[i][7]*A2b.w;
#pragma unroll
        for (int o = 8; o >= 1; o >>= 1) {
            t1 += __shfl_xor_sync(0xffffffffu, t1, o);
            t2 += __shfl_xor_sync(0xffffffffu, t2, o);
        }
        if ((tid & 15) == 0) {
            S1[(size_t)b * NN + row0 + tm + i] = t1;
            S2[(size_t)b * NN + row0 + tm + i] = t2;
        }
    }
}

// ---------------- Kernel F: fused softmax + aggregation + residual ----------------
// grid (NN/64, B) = 256 blocks, 128 threads (4 warps). Warp tile 16m x 128n.
// p computed inline into mma A fragments; l accumulated per-lane; out = x + acc/l.
// dyn smem: s2[2048] f32 (8192 B) | mask[64][65] u32 (16640 B) | Bbuf 2x8192 B.
__global__ __launch_bounds__(128, 2) void k_fused(
    const __nv_bfloat16* __restrict__ HT, const uint32_t* __restrict__ MASK,
    const float* __restrict__ S1, const float* __restrict__ S2,
    const float* __restrict__ Xin, float* __restrict__ Xout)
{
    extern __shared__ char sm[];
    float*    s2s = (float*)sm;                       // [2048]
    uint32_t* msk = (uint32_t*)(sm + 8192);           // [64*65]
    const uint32_t sb_base = smem_u32(sm + 8192 + 16640);
    __shared__ float s_red[4];

    const int b    = blockIdx.y;
    const int i0   = blockIdx.x * 64;
    const int tid  = threadIdx.x;
    const int warp = tid >> 5;
    const int lane = tid & 31;

    // ---- load s2 to smem + block max (unmasked; softmax shift-invariant)
    const float* s2g = S2 + (size_t)b * NN;
    float mx;
    {
        float4 v0 = *(const float4*)(s2g + tid * 16);
        float4 v1 = *(const float4*)(s2g + tid * 16 + 4);
        float4 v2 = *(const float4*)(s2g + tid * 16 + 8);
        float4 v3 = *(const float4*)(s2g + tid * 16 + 12);
        *(float4*)(s2s + tid * 16)      = v0;
        *(float4*)(s2s + tid * 16 + 4)  = v1;
        *(float4*)(s2s + tid * 16 + 8)  = v2;
        *(float4*)(s2s + tid * 16 + 12) = v3;
        mx = fmaxf(fmaxf(fmaxf(v0.x, v0.y), fmaxf(v0.z, v0.w)),
                   fmaxf(fmaxf(v1.x, v1.y), fmaxf(v1.z, v1.w)));
        mx = fmaxf(mx, fmaxf(fmaxf(v2.x, v2.y), fmaxf(v2.z, v2.w)));
        mx = fmaxf(mx, fmaxf(fmaxf(v3.x, v3.y), fmaxf(v3.z, v3.w)));
#pragma unroll
        for (int o = 16; o > 0; o >>= 1)
            mx = fmaxf(mx, __shfl_xor_sync(0xffffffffu, mx, o));
        if (lane == 0) s_red[warp] = mx;
    }
    // ---- load bitmask rows i0..i0+63 (stride 65 words in smem, conflict-free)
    {
        const uint32_t* mg = MASK + ((size_t)b * NN + i0) * 64;
#pragma unroll
        for (int k = 0; k < 32; k++) {
            int idx = tid + k * 128;          // 0..4095
            int r = idx >> 6, w = idx & 63;
            msk[r * 65 + w] = mg[idx];
        }
    }
    __syncthreads();
    mx = fmaxf(fmaxf(s_red[0], s_red[1]), fmaxf(s_red[2], s_red[3]));

    // ---- per-lane rows + softmax shift
    const int r_lo = warp * 16 + (lane >> 2);
    const int r_hi = r_lo + 8;
    const float s1_lo = S1[(size_t)b * NN + i0 + r_lo];
    const float s1_hi = S1[(size_t)b * NN + i0 + r_hi];
    float t;
    t = s1_lo + mx; const float m_lo = fmaxf(t, LRELU_ALPHA * t);
    t = s1_hi + mx; const float m_hi = fmaxf(t, LRELU_ALPHA * t);

    const int jb = (lane & 3) * 2;
    const int lr = lane & 15;
    const int lc = lane >> 4;
    const uint32_t offB0 = swz(lr, lc);
    const uint32_t offB1 = swz(lr, 2 + lc);

    const char* Hb = (const char*)(HT + (size_t)b * DD * NN);

    float acc[16][4];
#pragma unroll
    for (int nt = 0; nt < 16; nt++)
#pragma unroll
        for (int q = 0; q < 4; q++) acc[nt][q] = 0.f;
    float l_lo = 0.f, l_hi = 0.f;

    // prefetch B chunk 0 (128 d-rows x 32 j bf16, swizzled)
#pragma unroll
    for (int p = 0; p < 4; p++) {
        int sidx = tid + p * 128;
        int r = sidx >> 2, c = sidx & 3;
        cpasync16(sb_base + swz(r, c), Hb + (size_t)r * (NN * 2) + c * 16);
    }
    cp_commit();

    for (int kc = 0; kc < 64; kc++) {
        if (kc < 63) {
            const uint32_t dB = sb_base + ((kc + 1) & 1) * 8192;
            const size_t koff = (size_t)(kc + 1) * 64;
#pragma unroll
            for (int p = 0; p < 4; p++) {
                int sidx = tid + p * 128;
                int r = sidx >> 2, c = sidx & 3;
                cpasync16(dB + swz(r, c), Hb + (size_t)r * (NN * 2) + koff + c * 16);
            }
            cp_commit();
            asm volatile("cp.async.wait_group 1;" ::: "memory");
        } else {
            asm volatile("cp.async.wait_group 0;" ::: "memory");
        }
        __syncthreads();

        const uint32_t sB = sb_base + (kc & 1) * 8192;
        const uint32_t wl_full = msk[r_lo * 65 + kc];
        const uint32_t wh_full = msk[r_hi * 65 + kc];
#pragma unroll
        for (int s = 0; s < 2; s++) {
            const uint32_t wl = wl_full >> (s * 16);
            const uint32_t wh = wh_full >> (s * 16);
            const float2 v0 = *(const float2*)(s2s + kc * 32 + s * 16 + jb);
            const float2 v8 = *(const float2*)(s2s + kc * 32 + s * 16 + jb + 8);

            float z;
            z = s1_lo + v0.x; z = fmaxf(z, LRELU_ALPHA * z);
            float p00 = __expf(z - m_lo); if (!(wl & (1u << (jb + 0)))) p00 = 0.f;
            z = s1_lo + v0.y; z = fmaxf(z, LRELU_ALPHA * z);
            float p01 = __expf(z - m_lo); if (!(wl & (1u << (jb + 1)))) p01 = 0.f;
            z = s1_lo + v8.x; z = fmaxf(z, LRELU_ALPHA * z);
            float p08 = __expf(z - m_lo); if (!(wl & (1u << (jb + 8)))) p08 = 0.f;
            z = s1_lo + v8.y; z = fmaxf(z, LRELU_ALPHA * z);
            float p09 = __expf(z - m_lo); if (!(wl & (1u << (jb + 9)))) p09 = 0.f;
            z = s1_hi + v0.x; z = fmaxf(z, LRELU_ALPHA * z);
            float p10 = __expf(z - m_hi); if (!(wh & (1u << (jb + 0)))) p10 = 0.f;
            z = s1_hi + v0.y; z = fmaxf(z, LRELU_ALPHA * z);
            float p11 = __expf(z - m_hi); if (!(wh & (1u << (jb + 1)))) p11 = 0.f;
            z = s1_hi + v8.x; z = fmaxf(z, LRELU_ALPHA * z);
            float p18 = __expf(z - m_hi); if (!(wh & (1u << (jb + 8)))) p18 = 0.f;
            z = s1_hi + v8.y; z = fmaxf(z, LRELU_ALPHA * z);
            float p19 = __expf(z - m_hi); if (!(wh & (1u << (jb + 9)))) p19 = 0.f;

            l_lo += (p00 + p01) + (p08 + p09);
            l_hi += (p10 + p11) + (p18 + p19);

            uint32_t a[4];
            a[0] = pack_bf16x2(p00, p01);
            a[1] = pack_bf16x2(p10, p11);
            a[2] = pack_bf16x2(p08, p09);
            a[3] = pack_bf16x2(p18, p19);

            const uint32_t off = (s == 0) ? offB0 : offB1;
#pragma unroll
            for (int nt = 0; nt < 8; nt++) {
                uint32_t q[4];
                ldm4(q, sB + off + nt * 1024);
                mma_bf16(acc[2 * nt + 0], a, q[0], q[2]);
                mma_bf16(acc[2 * nt + 1], a, q[1], q[3]);
            }
        }
        __syncthreads();
    }

    // ---- finalize l (quad reduce), epilogue out = x + acc/l
    l_lo += __shfl_xor_sync(0xffffffffu, l_lo, 1);
    l_lo += __shfl_xor_sync(0xffffffffu, l_lo, 2);
    l_hi += __shfl_xor_sync(0xffffffffu, l_hi, 1);
    l_hi += __shfl_xor_sync(0xffffffffu, l_hi, 2);
    const float inv_lo = 1.0f / l_lo;
    const float inv_hi = 1.0f / l_hi;

    const size_t ro_lo = ((size_t)b * NN + i0 + r_lo) * DD;
    const size_t ro_hi = ((size_t)b * NN + i0 + r_hi) * DD;
#pragma unroll
    for (int nt = 0; nt < 16; nt++) {
        const int c = nt * 8 + jb;
        float2 xa = *(const float2*)(Xin + ro_lo + c);
        float2 xb = *(const float2*)(Xin + ro_hi + c);
        float2 oa, ob;
        oa.x = xa.x + acc[nt][0] * inv_lo;
        oa.y = xa.y + acc[nt][1] * inv_lo;
        ob.x = xb.x + acc[nt][2] * inv_hi;
        ob.y = xb.y + acc[nt][3] * inv_hi;
        *(float2*)(Xout + ro_lo + c) = oa;
        *(float2*)(Xout + ro_hi + c) = ob;
    }
}

// ---------------- host launcher ----------------
extern "C" void kernel_launch(void* const* d_in, const int* in_sizes, int n_in,
                              void* d_out, int out_size)
{
    (void)in_sizes; (void)n_in; (void)out_size;
    const float* x   = (const float*)d_in[0];
    const int*   adj = (const int*)d_in[1];
    const float* Wg  = (const float*)d_in[2];
    const float* bg  = (const float*)d_in[3];
    const float* aa  = (const float*)d_in[4];
    float* out = (float*)d_out;

    float *xbuf, *s1, *s2;
    __nv_bfloat16 *hT;
    uint32_t *msk;
    cudaGetSymbolAddress((void**)&xbuf, g_x);
    cudaGetSymbolAddress((void**)&s1,   g_s1);
    cudaGetSymbolAddress((void**)&s2,   g_s2);
    cudaGetSymbolAddress((void**)&hT,   g_hT);
    cudaGetSymbolAddress((void**)&msk,  g_mask);

    const int smemF = 8192 + 16640 + 2 * 8192;   // 41216 B

    k_pack<<<dim3(NN / 8, BATCH), 256>>>(adj, msk);

    for (int l = 0; l < 3; l++) {
        const float* xin  = (l == 0) ? x : xbuf;
        float*       xout = (l == 2) ? out : xbuf;
        k_gemm_relu<<<dim3(NN / 64, BATCH), 128>>>(
            xin, Wg + (size_t)l * DD * DD, bg + (size_t)l * DD,
            aa + (size_t)l * 2 * DD, aa + (size_t)l * 2 * DD + DD,
            hT, s1, s2);
        k_fused<<<dim3(NN / 64, BATCH), 128, smemF>>>(hT, msk, s1, s2, xin, xout);
    }
}

// round 11
// speedup vs baseline: 6.8390x; 1.2487x over previous
#include <cuda_runtime.h>
#include <cuda_bf16.h>
#include <cstdint>

#define BATCH 8
#define NN    2048
#define DD    128
#define LRELU_ALPHA 0.2f

// ---------------- device scratch (no allocation allowed) ----------------
__device__ __nv_bfloat16 g_hT[BATCH * DD * NN];   // transposed h, bf16 (B operand)
__device__ float g_x[BATCH * NN * DD];            // residual ping-pong
__device__ float g_s1[BATCH * NN];
__device__ float g_s2[BATCH * NN];
__device__ uint32_t g_mask[(size_t)BATCH * NN * (NN / 32)];   // adj bitmask, 4 MB

// ---------------- helpers ----------------
__device__ __forceinline__ uint32_t smem_u32(const void* p) {
    uint32_t a;
    asm("{ .reg .u64 t; cvta.to.shared.u64 t, %1; cvt.u32.u64 %0, t; }"
        : "=r"(a) : "l"(p));
    return a;
}
__device__ __forceinline__ void cpasync16(uint32_t dst, const void* src) {
    asm volatile("cp.async.cg.shared.global [%0], [%1], 16;"
                 :: "r"(dst), "l"(src) : "memory");
}
__device__ __forceinline__ void cp_commit() {
    asm volatile("cp.async.commit_group;" ::: "memory");
}
__device__ __forceinline__ void ldm4(uint32_t* r, uint32_t addr) {
    asm volatile("ldmatrix.sync.aligned.m8n8.x4.shared.b16 {%0,%1,%2,%3}, [%4];"
                 : "=r"(r[0]), "=r"(r[1]), "=r"(r[2]), "=r"(r[3]) : "r"(addr));
}
__device__ __forceinline__ void mma_bf16(float* c, const uint32_t* a,
                                         uint32_t b0, uint32_t b1) {
    asm volatile(
        "mma.sync.aligned.m16n8k16.row.col.f32.bf16.bf16.f32 "
        "{%0,%1,%2,%3}, {%4,%5,%6,%7}, {%8,%9}, {%0,%1,%2,%3};"
        : "+f"(c[0]), "+f"(c[1]), "+f"(c[2]), "+f"(c[3])
        : "r"(a[0]), "r"(a[1]), "r"(a[2]), "r"(a[3]), "r"(b0), "r"(b1));
}
__device__ __forceinline__ void mma_tf32(float* c, const uint32_t* a,
                                         uint32_t b0, uint32_t b1) {
    asm volatile(
        "mma.sync.aligned.m16n8k8.row.col.f32.tf32.tf32.f32 "
        "{%0,%1,%2,%3}, {%4,%5,%6,%7}, {%8,%9}, {%0,%1,%2,%3};"
        : "+f"(c[0]), "+f"(c[1]), "+f"(c[2]), "+f"(c[3])
        : "r"(a[0]), "r"(a[1]), "r"(a[2]), "r"(a[3]), "r"(b0), "r"(b1));
}
__device__ __forceinline__ uint32_t f2tf32(float v) {
    uint32_t r;
    asm("cvt.rna.tf32.f32 %0, %1;" : "=r"(r) : "f"(v));
    return r;
}
// swizzled byte offset of 16B chunk c (0..3) of row r in a [rows][32 bf16] tile
__device__ __forceinline__ uint32_t swz(int r, int c) {
    return (uint32_t)(r * 64 + (((c) ^ ((r >> 1) & 3)) << 4));
}
// pack two floats to bf16x2 {lo, hi}
__device__ __forceinline__ uint32_t pack_bf16x2(float lo, float hi) {
    uint32_t r;
    asm("cvt.rn.bf16x2.f32 %0, %1, %2;" : "=r"(r) : "f"(hi), "f"(lo));
    return r;
}

// ---------------- Kernel PK: pack adj into bitmask (runs ONCE) ----------------
// FIX vs prior round: strided scalar loads so each ballot covers 32 CONSECUTIVE
// j (bit L of word w*4+c == element w*128 + 32c + L). The int4 version permuted
// bits (word held elements {0,4,...,124}) -> rel_err 1.9e-2.
__global__ __launch_bounds__(256) void k_pack(
    const int* __restrict__ ADJ, uint32_t* __restrict__ M)
{
    const int b    = blockIdx.y;
    const int row  = blockIdx.x * 8 + (threadIdx.x >> 5);
    const int lane = threadIdx.x & 31;
    const int* ar = ADJ + ((size_t)b * NN + row) * NN;
    uint32_t* mr  = M + ((size_t)b * NN + row) * (NN / 32);
#pragma unroll 4
    for (int w = 0; w < 16; w++) {
        int v0 = __ldg(ar + w * 128 +  0 + lane);
        int v1 = __ldg(ar + w * 128 + 32 + lane);
        int v2 = __ldg(ar + w * 128 + 64 + lane);
        int v3 = __ldg(ar + w * 128 + 96 + lane);
        uint32_t b0 = __ballot_sync(0xffffffffu, v0 != 0);
        uint32_t b1 = __ballot_sync(0xffffffffu, v1 != 0);
        uint32_t b2 = __ballot_sync(0xffffffffu, v2 != 0);
        uint32_t b3 = __ballot_sync(0xffffffffu, v3 != 0);
        if (lane == 0) *(uint4*)(mr + w * 4) = make_uint4(b0, b1, b2, b3);
    }
}

// ---------------- Kernel H: h = relu(x@W+b) via tf32 mma; HT bf16 + s1/s2 -------
// grid (NN/64, B), 128 thr, 4 warps x (16m x 128n), K=128 in 4 chunks of 32.
// dyn smem: sX tf32 [64][132] (33792 B) | sW tf32 [32][132] (16896 B, reused as
// sHT bf16 [128][66] in the epilogue). Total 50688 B.
__global__ __launch_bounds__(128) void k_h(
    const float* __restrict__ X, const float* __restrict__ W,
    const float* __restrict__ bias,
    const float* __restrict__ a1, const float* __restrict__ a2,
    __nv_bfloat16* __restrict__ HT,
    float* __restrict__ S1, float* __restrict__ S2)
{
    extern __shared__ char sm[];
    uint32_t* sX = (uint32_t*)sm;                       // [64][132]
    uint32_t* sW = (uint32_t*)(sm + 33792);             // [32][132]
    __nv_bfloat16* sHT = (__nv_bfloat16*)(sm + 33792);  // [128][66] (reuse)

    const int b   = blockIdx.y;
    const int i0  = blockIdx.x * 64;
    const int tid = threadIdx.x;
    const int warp = tid >> 5;
    const int lane = tid & 31;

    // stage x tile -> tf32 smem
    const float* Xb = X + ((size_t)b * NN + i0) * DD;
#pragma unroll
    for (int p = 0; p < 16; p++) {
        int gidx = p * 128 + tid;            // float4 units
        int row  = gidx >> 5;
        int c4   = (gidx & 31) << 2;
        float4 v = *(const float4*)(Xb + (size_t)row * DD + c4);
        uint32_t t0 = f2tf32(v.x), t1 = f2tf32(v.y), t2 = f2tf32(v.z), t3 = f2tf32(v.w);
        *(uint4*)&sX[row * 132 + c4] = make_uint4(t0, t1, t2, t3);
    }

    float acc[16][4];
#pragma unroll
    for (int nt = 0; nt < 16; nt++)
#pragma unroll
        for (int q = 0; q < 4; q++) acc[nt][q] = 0.f;

    const int rq = lane >> 2;       // 0..7
    const int kq = lane & 3;        // 0..3

    for (int kc = 0; kc < 4; kc++) {
        __syncthreads();
        // stage W chunk rows kc*32..+31 -> tf32 smem
#pragma unroll
        for (int p = 0; p < 8; p++) {
            int gidx = p * 128 + tid;        // float4 units
            int r    = gidx >> 5;
            int c4   = (gidx & 31) << 2;
            float4 v = *(const float4*)(W + (size_t)(kc * 32 + r) * DD + c4);
            uint32_t t0 = f2tf32(v.x), t1 = f2tf32(v.y), t2 = f2tf32(v.z), t3 = f2tf32(v.w);
            *(uint4*)&sW[r * 132 + c4] = make_uint4(t0, t1, t2, t3);
        }
        __syncthreads();
#pragma unroll
        for (int k8 = 0; k8 < 4; k8++) {
            const int kkA = kc * 32 + k8 * 8 + kq;    // col in sX
            const int r0  = warp * 16 + rq;
            uint32_t a[4];
            a[0] = sX[r0 * 132 + kkA];
            a[1] = sX[(r0 + 8) * 132 + kkA];
            a[2] = sX[r0 * 132 + kkA + 4];
            a[3] = sX[(r0 + 8) * 132 + kkA + 4];
            const int kwB = k8 * 8 + kq;              // row in sW
#pragma unroll
            for (int nt = 0; nt < 16; nt++) {
                const int n0 = nt * 8 + rq;
                uint32_t b0 = sW[kwB * 132 + n0];
                uint32_t b1 = sW[(kwB + 4) * 132 + n0];
                mma_tf32(acc[nt], a, b0, b1);
            }
        }
    }
    __syncthreads();   // sW dead; sHT reuse begins

    // epilogue: bias+relu, s1/s2 dots, stage h^T in smem
    const int rsm_lo = warp * 16 + rq;
    const int rsm_hi = rsm_lo + 8;
    float sum1_lo = 0.f, sum1_hi = 0.f, sum2_lo = 0.f, sum2_hi = 0.f;
#pragma unroll
    for (int nt = 0; nt < 16; nt++) {
        const int c = nt * 8 + kq * 2;
        float bi0 = __ldg(bias + c), bi1 = __ldg(bias + c + 1);
        float h00 = fmaxf(acc[nt][0] + bi0, 0.f);
        float h01 = fmaxf(acc[nt][1] + bi1, 0.f);
        float h10 = fmaxf(acc[nt][2] + bi0, 0.f);
        float h11 = fmaxf(acc[nt][3] + bi1, 0.f);
        float2 A1 = *(const float2*)(a1 + c);
        float2 A2 = *(const float2*)(a2 + c);
        sum1_lo += h00 * A1.x + h01 * A1.y;
        sum1_hi += h10 * A1.x + h11 * A1.y;
        sum2_lo += h00 * A2.x + h01 * A2.y;
        sum2_hi += h10 * A2.x + h11 * A2.y;
        sHT[c * 66 + rsm_lo]       = __float2bfloat16(h00);
        sHT[(c + 1) * 66 + rsm_lo] = __float2bfloat16(h01);
        sHT[c * 66 + rsm_hi]       = __float2bfloat16(h10);
        sHT[(c + 1) * 66 + rsm_hi] = __float2bfloat16(h11);
    }
#pragma unroll
    for (int o = 1; o <= 2; o <<= 1) {
        sum1_lo += __shfl_xor_sync(0xffffffffu, sum1_lo, o);
        sum1_hi += __shfl_xor_sync(0xffffffffu, sum1_hi, o);
        sum2_lo += __shfl_xor_sync(0xffffffffu, sum2_lo, o);
        sum2_hi += __shfl_xor_sync(0xffffffffu, sum2_hi, o);
    }
    if (kq == 0) {
        S1[(size_t)b * NN + i0 + rsm_lo] = sum1_lo;
        S1[(size_t)b * NN + i0 + rsm_hi] = sum1_hi;
        S2[(size_t)b * NN + i0 + rsm_lo] = sum2_lo;
        S2[(size_t)b * NN + i0 + rsm_hi] = sum2_hi;
    }
    __syncthreads();

    // coalesced transposed writeout: thread = d row
    const uint32_t sbase = smem_u32(sHT) + tid * 132;
    __nv_bfloat16* gdst = HT + ((size_t)b * DD + tid) * NN + i0;
#pragma unroll
    for (int g = 0; g < 8; g++) {
        uint32_t o0, o1, o2, o3;
        asm("ld.shared.b32 %0, [%1];" : "=r"(o0) : "r"(sbase + g * 16 + 0));
        asm("ld.shared.b32 %0, [%1];" : "=r"(o1) : "r"(sbase + g * 16 + 4));
        asm("ld.shared.b32 %0, [%1];" : "=r"(o2) : "r"(sbase + g * 16 + 8));
        asm("ld.shared.b32 %0, [%1];" : "=r"(o3) : "r"(sbase + g * 16 + 12));
        *(uint4*)((char*)gdst + g * 16) = make_uint4(o0, o1, o2, o3);
    }
}

// ---------------- Kernel F: fused softmax + aggregation + residual ----------------
// grid (NN/64, B), 256 threads (8 warps). 4 groups of 16 rows; each group has two
// warps splitting the 64 K-chunks by parity. 4-buffer cp.async ring. 2-pass smem
// reduction of accumulators + l at the end.
// dyn smem: s2[2048] f32 (8192) | mask[64][65] u32 (16640) | 4 x 8192 B buffers.
__global__ __launch_bounds__(256, 2) void k_fused(
    const __nv_bfloat16* __restrict__ HT, const uint32_t* __restrict__ MASK,
    const float* __restrict__ S1, const float* __restrict__ S2,
    const float* __restrict__ Xin, float* __restrict__ Xout)
{
    extern __shared__ char sm[];
    float*    s2s = (float*)sm;                       // [2048]
    uint32_t* msk = (uint32_t*)(sm + 8192);           // [64*65]
    char*     bufs = sm + 8192 + 16640;               // 4 x 8192
    const uint32_t sb_base = smem_u32(bufs);
    __shared__ float s_red[8];

    const int b    = blockIdx.y;
    const int i0   = blockIdx.x * 64;
    const int tid  = threadIdx.x;
    const int warp = tid >> 5;
    const int lane = tid & 31;
    const int group  = warp & 3;
    const int parity = warp >> 2;

    // ---- load s2 to smem + block max (unmasked; softmax shift-invariant)
    const float* s2g = S2 + (size_t)b * NN;
    float mx;
    {
        float4 v0 = *(const float4*)(s2g + tid * 8);
        float4 v1 = *(const float4*)(s2g + tid * 8 + 4);
        *(float4*)(s2s + tid * 8)     = v0;
        *(float4*)(s2s + tid * 8 + 4) = v1;
        mx = fmaxf(fmaxf(fmaxf(v0.x, v0.y), fmaxf(v0.z, v0.w)),
                   fmaxf(fmaxf(v1.x, v1.y), fmaxf(v1.z, v1.w)));
#pragma unroll
        for (int o = 16; o > 0; o >>= 1)
            mx = fmaxf(mx, __shfl_xor_sync(0xffffffffu, mx, o));
        if (lane == 0) s_red[warp] = mx;
    }
    // ---- load bitmask rows i0..i0+63 (stride 65 words)
    {
        const uint32_t* mg = MASK + ((size_t)b * NN + i0) * 64;
#pragma unroll
        for (int k = 0; k < 16; k++) {
            int idx = tid + k * 256;
            int r = idx >> 6, w = idx & 63;
            msk[r * 65 + w] = mg[idx];
        }
    }
    __syncthreads();
    mx = fmaxf(fmaxf(fmaxf(s_red[0], s_red[1]), fmaxf(s_red[2], s_red[3])),
               fmaxf(fmaxf(s_red[4], s_red[5]), fmaxf(s_red[6], s_red[7])));

    // ---- per-lane rows + softmax shift
    const int r_lo = group * 16 + (lane >> 2);
    const int r_hi = r_lo + 8;
    const float s1_lo = S1[(size_t)b * NN + i0 + r_lo];
    const float s1_hi = S1[(size_t)b * NN + i0 + r_hi];
    float t;
    t = s1_lo + mx; const float m_lo = fmaxf(t, LRELU_ALPHA * t);
    t = s1_hi + mx; const float m_hi = fmaxf(t, LRELU_ALPHA * t);

    const int jb = (lane & 3) * 2;
    const int lr = lane & 15;
    const int lc = lane >> 4;
    const uint32_t offB0 = swz(lr, lc);
    const uint32_t offB1 = swz(lr, 2 + lc);

    const char* Hb = (const char*)(HT + (size_t)b * DD * NN);

    float acc[16][4];
#pragma unroll
    for (int nt = 0; nt < 16; nt++)
#pragma unroll
        for (int q = 0; q < 4; q++) acc[nt][q] = 0.f;
    float l_lo = 0.f, l_hi = 0.f;

    // prefetch step 0 (chunks 0,1 -> buffers 0,1)
#pragma unroll
    for (int q = 0; q < 4; q++) {
        const int ch = q >> 1;
        const int sidx = tid + (q & 1) * 256;
        const int r = sidx >> 2, cc = sidx & 3;
        cpasync16(sb_base + ch * 8192 + swz(r, cc),
                  Hb + (size_t)r * (NN * 2) + ch * 64 + cc * 16);
    }
    cp_commit();

    for (int s = 0; s < 32; s++) {
        if (s < 31) {
            const int chbase = 2 * (s + 1);
            const uint32_t pairbuf = (uint32_t)(((s + 1) & 1) * 2);
#pragma unroll
            for (int q = 0; q < 4; q++) {
                const int ch = q >> 1;
                const int sidx = tid + (q & 1) * 256;
                const int r = sidx >> 2, cc = sidx & 3;
                cpasync16(sb_base + (pairbuf + ch) * 8192 + swz(r, cc),
                          Hb + (size_t)r * (NN * 2) + (size_t)(chbase + ch) * 64 + cc * 16);
            }
            cp_commit();
            asm volatile("cp.async.wait_group 1;" ::: "memory");
        } else {
            asm volatile("cp.async.wait_group 0;" ::: "memory");
        }
        __syncthreads();

        const int kc = 2 * s + parity;
        const uint32_t sB = sb_base + (uint32_t)(((s & 1) * 2 + parity) * 8192);
        const uint32_t wl_full = msk[r_lo * 65 + kc];
        const uint32_t wh_full = msk[r_hi * 65 + kc];
#pragma unroll
        for (int ss = 0; ss < 2; ss++) {
            const uint32_t wl = wl_full >> (ss * 16);
            const uint32_t wh = wh_full >> (ss * 16);
            const float2 v0 = *(const float2*)(s2s + kc * 32 + ss * 16 + jb);
            const float2 v8 = *(const float2*)(s2s + kc * 32 + ss * 16 + jb + 8);

            float z;
            z = s1_lo + v0.x; z = fmaxf(z, LRELU_ALPHA * z);
            float p00 = __expf(z - m_lo); if (!(wl & (1u << (jb + 0)))) p00 = 0.f;
            z = s1_lo + v0.y; z = fmaxf(z, LRELU_ALPHA * z);
            float p01 = __expf(z - m_lo); if (!(wl & (1u << (jb + 1)))) p01 = 0.f;
            z = s1_lo + v8.x; z = fmaxf(z, LRELU_ALPHA * z);
            float p08 = __expf(z - m_lo); if (!(wl & (1u << (jb + 8)))) p08 = 0.f;
            z = s1_lo + v8.y; z = fmaxf(z, LRELU_ALPHA * z);
            float p09 = __expf(z - m_lo); if (!(wl & (1u << (jb + 9)))) p09 = 0.f;
            z = s1_hi + v0.x; z = fmaxf(z, LRELU_ALPHA * z);
            float p10 = __expf(z - m_hi); if (!(wh & (1u << (jb + 0)))) p10 = 0.f;
            z = s1_hi + v0.y; z = fmaxf(z, LRELU_ALPHA * z);
            float p11 = __expf(z - m_hi); if (!(wh & (1u << (jb + 1)))) p11 = 0.f;
            z = s1_hi + v8.x; z = fmaxf(z, LRELU_ALPHA * z);
            float p18 = __expf(z - m_hi); if (!(wh & (1u << (jb + 8)))) p18 = 0.f;
            z = s1_hi + v8.y; z = fmaxf(z, LRELU_ALPHA * z);
            float p19 = __expf(z - m_hi); if (!(wh & (1u << (jb + 9)))) p19 = 0.f;

            l_lo += (p00 + p01) + (p08 + p09);
            l_hi += (p10 + p11) + (p18 + p19);

            uint32_t a[4];
            a[0] = pack_bf16x2(p00, p01);
            a[1] = pack_bf16x2(p10, p11);
            a[2] = pack_bf16x2(p08, p09);
            a[3] = pack_bf16x2(p18, p19);

            const uint32_t off = (ss == 0) ? offB0 : offB1;
#pragma unroll
            for (int nt = 0; nt < 8; nt++) {
                uint32_t qf[4];
                ldm4(qf, sB + off + nt * 1024);
                mma_bf16(acc[2 * nt + 0], a, qf[0], qf[2]);
                mma_bf16(acc[2 * nt + 1], a, qf[1], qf[3]);
            }
        }
        __syncthreads();
    }

    // ---- quad-reduce l within warp
    l_lo += __shfl_xor_sync(0xffffffffu, l_lo, 1);
    l_lo += __shfl_xor_sync(0xffffffffu, l_lo, 2);
    l_hi += __shfl_xor_sync(0xffffffffu, l_hi, 1);
    l_hi += __shfl_xor_sync(0xffffffffu, l_hi, 2);

    // ---- 2-pass cross-parity reduction through smem (reuse buffer region)
    float* red = (float*)bufs;
    const int rbase = (group * 32 + lane) * 33;
    if (parity) {
#pragma unroll
        for (int nt = 0; nt < 8; nt++)
#pragma unroll
            for (int q = 0; q < 4; q++) red[rbase + nt * 4 + q] = acc[nt][q];
        red[rbase + 32] = l_lo;
    }
    __syncthreads();
    if (!parity) {
#pragma unroll
        for (int nt = 0; nt < 8; nt++)
#pragma unroll
            for (int q = 0; q < 4; q++) acc[nt][q] += red[rbase + nt * 4 + q];
        l_lo += red[rbase + 32];
    }
    __syncthreads();
    if (parity) {
#pragma unroll
        for (int nt = 8; nt < 16; nt++)
#pragma unroll
            for (int q = 0; q < 4; q++) red[rbase + (nt - 8) * 4 + q] = acc[nt][q];
        red[rbase + 32] = l_hi;
    }
    __syncthreads();
    if (!parity) {
#pragma unroll
        for (int nt = 8; nt < 16; nt++)
#pragma unroll
            for (int q = 0; q < 4; q++) acc[nt][q] += red[rbase + (nt - 8) * 4 + q];
        l_hi += red[rbase + 32];

        const float inv_lo = 1.0f / l_lo;
        const float inv_hi = 1.0f / l_hi;
        const size_t ro_lo = ((size_t)b * NN + i0 + r_lo) * DD;
        const size_t ro_hi = ((size_t)b * NN + i0 + r_hi) * DD;
#pragma unroll
        for (int nt = 0; nt < 16; nt++) {
            const int c = nt * 8 + jb;
            float2 xa = *(const float2*)(Xin + ro_lo + c);
            float2 xb = *(const float2*)(Xin + ro_hi + c);
            float2 oa, ob;
            oa.x = xa.x + acc[nt][0] * inv_lo;
            oa.y = xa.y + acc[nt][1] * inv_lo;
            ob.x = xb.x + acc[nt][2] * inv_hi;
            ob.y = xb.y + acc[nt][3] * inv_hi;
            *(float2*)(Xout + ro_lo + c) = oa;
            *(float2*)(Xout + ro_hi + c) = ob;
        }
    }
}

// ---------------- host launcher ----------------
extern "C" void kernel_launch(void* const* d_in, const int* in_sizes, int n_in,
                              void* d_out, int out_size)
{
    (void)in_sizes; (void)n_in; (void)out_size;
    const float* x   = (const float*)d_in[0];
    const int*   adj = (const int*)d_in[1];
    const float* Wg  = (const float*)d_in[2];
    const float* bg  = (const float*)d_in[3];
    const float* aa  = (const float*)d_in[4];
    float* out = (float*)d_out;

    float *xbuf, *s1, *s2;
    __nv_bfloat16 *hT;
    uint32_t *msk;
    cudaGetSymbolAddress((void**)&xbuf, g_x);
    cudaGetSymbolAddress((void**)&s1,   g_s1);
    cudaGetSymbolAddress((void**)&s2,   g_s2);
    cudaGetSymbolAddress((void**)&hT,   g_hT);
    cudaGetSymbolAddress((void**)&msk,  g_mask);

    const int smemH = 33792 + 16896;                      // 50688 B
    const int smemF = 8192 + 16640 + 4 * 8192;            // 57600 B
    cudaFuncSetAttribute(k_h,     cudaFuncAttributeMaxDynamicSharedMemorySize, smemH);
    cudaFuncSetAttribute(k_fused, cudaFuncAttributeMaxDynamicSharedMemorySize, smemF);

    k_pack<<<dim3(NN / 8, BATCH), 256>>>(adj, msk);

    for (int l = 0; l < 3; l++) {
        const float* xin  = (l == 0) ? x : xbuf;
        float*       xout = (l == 2) ? out : xbuf;
        k_h<<<dim3(NN / 64, BATCH), 128, smemH>>>(
            xin, Wg + (size_t)l * DD * DD, bg + (size_t)l * DD,
            aa + (size_t)l * 2 * DD, aa + (size_t)l * 2 * DD + DD,
            hT, s1, s2);
        k_fused<<<dim3(NN / 64, BATCH), 256, smemF>>>(hT, msk, s1, s2, xin, xout);
    }
}

// round 12
// speedup vs baseline: 7.0500x; 1.0309x over previous
#include <cuda_runtime.h>
#include <cuda_bf16.h>
#include <cstdint>

#define BATCH 8
#define NN    2048
#define DD    128
#define LRELU_ALPHA 0.2f

// ---------------- device scratch (no allocation allowed) ----------------
__device__ __nv_bfloat16 g_hT[BATCH * DD * NN];   // transposed h, bf16 (B operand)
__device__ float g_x[BATCH * NN * DD];            // residual ping-pong
__device__ float g_s1[BATCH * NN];
__device__ float g_s2[BATCH * NN];
__device__ uint32_t g_mask[(size_t)BATCH * NN * (NN / 32)];   // adj bitmask, 4 MB

// ---------------- helpers ----------------
__device__ __forceinline__ uint32_t smem_u32(const void* p) {
    uint32_t a;
    asm("{ .reg .u64 t; cvta.to.shared.u64 t, %1; cvt.u32.u64 %0, t; }"
        : "=r"(a) : "l"(p));
    return a;
}
__device__ __forceinline__ void cpasync16(uint32_t dst, const void* src) {
    asm volatile("cp.async.cg.shared.global [%0], [%1], 16;"
                 :: "r"(dst), "l"(src) : "memory");
}
__device__ __forceinline__ void cp_commit() {
    asm volatile("cp.async.commit_group;" ::: "memory");
}
__device__ __forceinline__ void ldm4(uint32_t* r, uint32_t addr) {
    asm volatile("ldmatrix.sync.aligned.m8n8.x4.shared.b16 {%0,%1,%2,%3}, [%4];"
                 : "=r"(r[0]), "=r"(r[1]), "=r"(r[2]), "=r"(r[3]) : "r"(addr));
}
__device__ __forceinline__ void mma_bf16(float* c, const uint32_t* a,
                                         uint32_t b0, uint32_t b1) {
    asm volatile(
        "mma.sync.aligned.m16n8k16.row.col.f32.bf16.bf16.f32 "
        "{%0,%1,%2,%3}, {%4,%5,%6,%7}, {%8,%9}, {%0,%1,%2,%3};"
        : "+f"(c[0]), "+f"(c[1]), "+f"(c[2]), "+f"(c[3])
        : "r"(a[0]), "r"(a[1]), "r"(a[2]), "r"(a[3]), "r"(b0), "r"(b1));
}
__device__ __forceinline__ void mma_tf32(float* c, const uint32_t* a,
                                         uint32_t b0, uint32_t b1) {
    asm volatile(
        "mma.sync.aligned.m16n8k8.row.col.f32.tf32.tf32.f32 "
        "{%0,%1,%2,%3}, {%4,%5,%6,%7}, {%8,%9}, {%0,%1,%2,%3};"
        : "+f"(c[0]), "+f"(c[1]), "+f"(c[2]), "+f"(c[3])
        : "r"(a[0]), "r"(a[1]), "r"(a[2]), "r"(a[3]), "r"(b0), "r"(b1));
}
__device__ __forceinline__ uint32_t f2tf32(float v) {
    uint32_t r;
    asm("cvt.rna.tf32.f32 %0, %1;" : "=r"(r) : "f"(v));
    return r;
}
// swizzled byte offset of 16B chunk c (0..3) of row r in a [rows][32 bf16] tile
__device__ __forceinline__ uint32_t swz(int r, int c) {
    return (uint32_t)(r * 64 + (((c) ^ ((r >> 1) & 3)) << 4));
}
// pack two floats to bf16x2 {lo, hi}
__device__ __forceinline__ uint32_t pack_bf16x2(float lo, float hi) {
    uint32_t r;
    asm("cvt.rn.bf16x2.f32 %0, %1, %2;" : "=r"(r) : "f"(hi), "f"(lo));
    return r;
}

// ---------------- Kernel PK: pack adj into bitmask (runs ONCE) ----------------
// Strided scalar loads so each ballot covers 32 CONSECUTIVE j.
__global__ __launch_bounds__(256) void k_pack(
    const int* __restrict__ ADJ, uint32_t* __restrict__ M)
{
    const int b    = blockIdx.y;
    const int row  = blockIdx.x * 8 + (threadIdx.x >> 5);
    const int lane = threadIdx.x & 31;
    const int* ar = ADJ + ((size_t)b * NN + row) * NN;
    uint32_t* mr  = M + ((size_t)b * NN + row) * (NN / 32);
#pragma unroll 4
    for (int w = 0; w < 16; w++) {
        int v0 = __ldg(ar + w * 128 +  0 + lane);
        int v1 = __ldg(ar + w * 128 + 32 + lane);
        int v2 = __ldg(ar + w * 128 + 64 + lane);
        int v3 = __ldg(ar + w * 128 + 96 + lane);
        uint32_t b0 = __ballot_sync(0xffffffffu, v0 != 0);
        uint32_t b1 = __ballot_sync(0xffffffffu, v1 != 0);
        uint32_t b2 = __ballot_sync(0xffffffffu, v2 != 0);
        uint32_t b3 = __ballot_sync(0xffffffffu, v3 != 0);
        if (lane == 0) *(uint4*)(mr + w * 4) = make_uint4(b0, b1, b2, b3);
    }
}

// ---------------- Kernel H: h = relu(x@W+b) via tf32 mma; HT bf16 + s1/s2 -------
__global__ __launch_bounds__(128) void k_h(
    const float* __restrict__ X, const float* __restrict__ W,
    const float* __restrict__ bias,
    const float* __restrict__ a1, const float* __restrict__ a2,
    __nv_bfloat16* __restrict__ HT,
    float* __restrict__ S1, float* __restrict__ S2)
{
    extern __shared__ char sm[];
    uint32_t* sX = (uint32_t*)sm;                       // [64][132]
    uint32_t* sW = (uint32_t*)(sm + 33792);             // [32][132]
    __nv_bfloat16* sHT = (__nv_bfloat16*)(sm + 33792);  // [128][66] (reuse)

    const int b   = blockIdx.y;
    const int i0  = blockIdx.x * 64;
    const int tid = threadIdx.x;
    const int warp = tid >> 5;
    const int lane = tid & 31;

    const float* Xb = X + ((size_t)b * NN + i0) * DD;
#pragma unroll
    for (int p = 0; p < 16; p++) {
        int gidx = p * 128 + tid;
        int row  = gidx >> 5;
        int c4   = (gidx & 31) << 2;
        float4 v = *(const float4*)(Xb + (size_t)row * DD + c4);
        uint32_t t0 = f2tf32(v.x), t1 = f2tf32(v.y), t2 = f2tf32(v.z), t3 = f2tf32(v.w);
        *(uint4*)&sX[row * 132 + c4] = make_uint4(t0, t1, t2, t3);
    }

    float acc[16][4];
#pragma unroll
    for (int nt = 0; nt < 16; nt++)
#pragma unroll
        for (int q = 0; q < 4; q++) acc[nt][q] = 0.f;

    const int rq = lane >> 2;
    const int kq = lane & 3;

    for (int kc = 0; kc < 4; kc++) {
        __syncthreads();
#pragma unroll
        for (int p = 0; p < 8; p++) {
            int gidx = p * 128 + tid;
            int r    = gidx >> 5;
            int c4   = (gidx & 31) << 2;
            float4 v = *(const float4*)(W + (size_t)(kc * 32 + r) * DD + c4);
            uint32_t t0 = f2tf32(v.x), t1 = f2tf32(v.y), t2 = f2tf32(v.z), t3 = f2tf32(v.w);
            *(uint4*)&sW[r * 132 + c4] = make_uint4(t0, t1, t2, t3);
        }
        __syncthreads();
#pragma unroll
        for (int k8 = 0; k8 < 4; k8++) {
            const int kkA = kc * 32 + k8 * 8 + kq;
            const int r0  = warp * 16 + rq;
            uint32_t a[4];
            a[0] = sX[r0 * 132 + kkA];
            a[1] = sX[(r0 + 8) * 132 + kkA];
            a[2] = sX[r0 * 132 + kkA + 4];
            a[3] = sX[(r0 + 8) * 132 + kkA + 4];
            const int kwB = k8 * 8 + kq;
#pragma unroll
            for (int nt = 0; nt < 16; nt++) {
                const int n0 = nt * 8 + rq;
                uint32_t b0 = sW[kwB * 132 + n0];
                uint32_t b1 = sW[(kwB + 4) * 132 + n0];
                mma_tf32(acc[nt], a, b0, b1);
            }
        }
    }
    __syncthreads();

    const int rsm_lo = warp * 16 + rq;
    const int rsm_hi = rsm_lo + 8;
    float sum1_lo = 0.f, sum1_hi = 0.f, sum2_lo = 0.f, sum2_hi = 0.f;
#pragma unroll
    for (int nt = 0; nt < 16; nt++) {
        const int c = nt * 8 + kq * 2;
        float bi0 = __ldg(bias + c), bi1 = __ldg(bias + c + 1);
        float h00 = fmaxf(acc[nt][0] + bi0, 0.f);
        float h01 = fmaxf(acc[nt][1] + bi1, 0.f);
        float h10 = fmaxf(acc[nt][2] + bi0, 0.f);
        float h11 = fmaxf(acc[nt][3] + bi1, 0.f);
        float2 A1 = *(const float2*)(a1 + c);
        float2 A2 = *(const float2*)(a2 + c);
        sum1_lo += h00 * A1.x + h01 * A1.y;
        sum1_hi += h10 * A1.x + h11 * A1.y;
        sum2_lo += h00 * A2.x + h01 * A2.y;
        sum2_hi += h10 * A2.x + h11 * A2.y;
        sHT[c * 66 + rsm_lo]       = __float2bfloat16(h00);
        sHT[(c + 1) * 66 + rsm_lo] = __float2bfloat16(h01);
        sHT[c * 66 + rsm_hi]       = __float2bfloat16(h10);
        sHT[(c + 1) * 66 + rsm_hi] = __float2bfloat16(h11);
    }
#pragma unroll
    for (int o = 1; o <= 2; o <<= 1) {
        sum1_lo += __shfl_xor_sync(0xffffffffu, sum1_lo, o);
        sum1_hi += __shfl_xor_sync(0xffffffffu, sum1_hi, o);
        sum2_lo += __shfl_xor_sync(0xffffffffu, sum2_lo, o);
        sum2_hi += __shfl_xor_sync(0xffffffffu, sum2_hi, o);
    }
    if (kq == 0) {
        S1[(size_t)b * NN + i0 + rsm_lo] = sum1_lo;
        S1[(size_t)b * NN + i0 + rsm_hi] = sum1_hi;
        S2[(size_t)b * NN + i0 + rsm_lo] = sum2_lo;
        S2[(size_t)b * NN + i0 + rsm_hi] = sum2_hi;
    }
    __syncthreads();

    const uint32_t sbase = smem_u32(sHT) + tid * 132;
    __nv_bfloat16* gdst = HT + ((size_t)b * DD + tid) * NN + i0;
#pragma unroll
    for (int g = 0; g < 8; g++) {
        uint32_t o0, o1, o2, o3;
        asm("ld.shared.b32 %0, [%1];" : "=r"(o0) : "r"(sbase + g * 16 + 0));
        asm("ld.shared.b32 %0, [%1];" : "=r"(o1) : "r"(sbase + g * 16 + 4));
        asm("ld.shared.b32 %0, [%1];" : "=r"(o2) : "r"(sbase + g * 16 + 8));
        asm("ld.shared.b32 %0, [%1];" : "=r"(o3) : "r"(sbase + g * 16 + 12));
        *(uint4*)((char*)gdst + g * 16) = make_uint4(o0, o1, o2, o3);
    }
}

// ---------------- Kernel F: producer/consumer fused softmax+aggregation ---------
// grid (NN/64, B), 256 threads (8 warps): warps 0-3 producers, 4-7 consumers.
// Producers: exp/mask -> bf16 p-tile (2-buf), B cp.async ring (4-buf), row sums l.
// Consumers: pure ldmatrix+HMMA, each owns 32 d-cols x all 64 rows.
// dyn smem: s2s 8192 | sL 256 | msk 16640 | pbuf 2x4096 | Bbuf 4x8192 = 66048 B.
__global__ __launch_bounds__(256, 2) void k_fused(
    const __nv_bfloat16* __restrict__ HT, const uint32_t* __restrict__ MASK,
    const float* __restrict__ S1, const float* __restrict__ S2,
    const float* __restrict__ Xin, float* __restrict__ Xout)
{
    extern __shared__ char sm[];
    float*    s2s = (float*)sm;                       // [2048]
    float*    sL  = (float*)(sm + 8192);              // [64]
    uint32_t* msk = (uint32_t*)(sm + 8448);           // [64*65]
    const uint32_t pb = smem_u32(sm + 25088);         // 2 x 4096
    const uint32_t bb = smem_u32(sm + 33280);         // 4 x 8192
    __shared__ float s_red[8];

    const int b    = blockIdx.y;
    const int i0   = blockIdx.x * 64;
    const int tid  = threadIdx.x;
    const int warp = tid >> 5;
    const int lane = tid & 31;

    // ---- cooperative: s2 -> smem + global max; mask rows -> smem
    const float* s2g = S2 + (size_t)b * NN;
    float mx;
    {
        float4 v0 = *(const float4*)(s2g + tid * 8);
        float4 v1 = *(const float4*)(s2g + tid * 8 + 4);
        *(float4*)(s2s + tid * 8)     = v0;
        *(float4*)(s2s + tid * 8 + 4) = v1;
        mx = fmaxf(fmaxf(fmaxf(v0.x, v0.y), fmaxf(v0.z, v0.w)),
                   fmaxf(fmaxf(v1.x, v1.y), fmaxf(v1.z, v1.w)));
#pragma unroll
        for (int o = 16; o > 0; o >>= 1)
            mx = fmaxf(mx, __shfl_xor_sync(0xffffffffu, mx, o));
        if (lane == 0) s_red[warp] = mx;
    }
    {
        const uint32_t* mg = MASK + ((size_t)b * NN + i0) * 64;
#pragma unroll
        for (int k = 0; k < 16; k++) {
            int idx = tid + k * 256;
            int r = idx >> 6, w = idx & 63;
            msk[r * 65 + w] = mg[idx];
        }
    }
    __syncthreads();
    mx = fmaxf(fmaxf(fmaxf(s_red[0], s_red[1]), fmaxf(s_red[2], s_red[3])),
               fmaxf(fmaxf(s_red[4], s_red[5]), fmaxf(s_red[6], s_red[7])));

    const char* Hb = (const char*)(HT + (size_t)b * DD * NN);

    // ================= PRODUCER state =================
    const int prow = warp * 16 + (lane >> 1);   // producers: warps 0-3
    const int jh   = lane & 1;                  // j half (16 j each)
    float s1r = 0.f, m = 0.f, l0 = 0.f, l1 = 0.f;
    if (warp < 4) {
        s1r = S1[(size_t)b * NN + i0 + prow];
        float t = s1r + mx;
        m = fmaxf(t, LRELU_ALPHA * t);
    }
    const uint32_t pdst0 = pb + swz(prow, jh * 2);
    const uint32_t pdst1 = pb + swz(prow, jh * 2 + 1);

    // producer: compute p for chunk kc into pbuf[kc&1]
    auto produce = [&](int kc) {
        const uint32_t w = msk[prow * 65 + kc] >> (jh * 16);
        const float* sp = s2s + kc * 32 + jh * 16;
        float4 va = *(const float4*)(sp);
        float4 vb = *(const float4*)(sp + 4);
        float4 vc = *(const float4*)(sp + 8);
        float4 vd = *(const float4*)(sp + 12);
        float p[16];
        float z;
#define PCALC(i, val) \
        z = s1r + (val); z = fmaxf(z, LRELU_ALPHA * z); \
        z = __expf(z - m); p[i] = (w & (1u << (i))) ? z : 0.f;
        PCALC(0, va.x)  PCALC(1, va.y)  PCALC(2, va.z)  PCALC(3, va.w)
        PCALC(4, vb.x)  PCALC(5, vb.y)  PCALC(6, vb.z)  PCALC(7, vb.w)
        PCALC(8, vc.x)  PCALC(9, vc.y)  PCALC(10, vc.z) PCALC(11, vc.w)
        PCALC(12, vd.x) PCALC(13, vd.y) PCALC(14, vd.z) PCALC(15, vd.w)
#undef PCALC
        l0 += ((p[0] + p[1]) + (p[2] + p[3])) + ((p[4] + p[5]) + (p[6] + p[7]));
        l1 += ((p[8] + p[9]) + (p[10] + p[11])) + ((p[12] + p[13]) + (p[14] + p[15]));
        uint32_t r0 = pack_bf16x2(p[0], p[1]),  r1 = pack_bf16x2(p[2], p[3]);
        uint32_t r2 = pack_bf16x2(p[4], p[5]),  r3 = pack_bf16x2(p[6], p[7]);
        uint32_t r4 = pack_bf16x2(p[8], p[9]),  r5 = pack_bf16x2(p[10], p[11]);
        uint32_t r6 = pack_bf16x2(p[12], p[13]), r7 = pack_bf16x2(p[14], p[15]);
        const uint32_t bo = (uint32_t)(kc & 1) * 4096;
        asm volatile("st.shared.v4.b32 [%0], {%1,%2,%3,%4};"
                     :: "r"(pdst0 + bo), "r"(r0), "r"(r1), "r"(r2), "r"(r3));
        asm volatile("st.shared.v4.b32 [%0], {%1,%2,%3,%4};"
                     :: "r"(pdst1 + bo), "r"(r4), "r"(r5), "r"(r6), "r"(r7));
    };
    // producer: issue cp.async for B chunk ch (each producer thread 4x16B)
    auto loadB = [&](int ch) {
        const uint32_t dst = bb + (uint32_t)(ch & 3) * 8192;
        const size_t koff = (size_t)ch * 64;
#pragma unroll
        for (int q = 0; q < 4; q++) {
            int idx = tid + q * 128;
            int r = idx >> 2, c = idx & 3;
            cpasync16(dst + swz(r, c), Hb + (size_t)r * (NN * 2) + koff + c * 16);
        }
        cp_commit();
    };

    // ================= CONSUMER state =================
    const int cw = warp - 4;                    // consumers: warps 4-7, own 32 d-cols
    const int lr = lane & 15;
    const int lc = lane >> 4;
    uint32_t offA[4][2], offB[2][2];
#pragma unroll
    for (int mt = 0; mt < 4; mt++)
#pragma unroll
        for (int ss = 0; ss < 2; ss++)
            offA[mt][ss] = swz(mt * 16 + lr, 2 * ss + lc);
#pragma unroll
    for (int dg = 0; dg < 2; dg++)
#pragma unroll
        for (int ss = 0; ss < 2; ss++)
            offB[dg][ss] = swz(cw * 32 + dg * 16 + lr, 2 * ss + lc);

    float acc[4][4][4];
#pragma unroll
    for (int mt = 0; mt < 4; mt++)
#pragma unroll
        for (int n = 0; n < 4; n++)
#pragma unroll
            for (int q = 0; q < 4; q++) acc[mt][n][q] = 0.f;

    // ---- prologue: producers stage B0..B2 and p(0)
    if (warp < 4) {
        loadB(0); loadB(1); loadB(2);
        produce(0);
        asm volatile("cp.async.wait_group 2;" ::: "memory");
    }
    __syncthreads();

    // ---- main loop
    for (int s = 0; s < 64; s++) {
        if (warp < 4) {
            if (s < 61) loadB(s + 3);
            if (s < 63) produce(s + 1);
            if (s < 61)      { asm volatile("cp.async.wait_group 2;" ::: "memory"); }
            else if (s == 61){ asm volatile("cp.async.wait_group 1;" ::: "memory"); }
            else if (s == 62){ asm volatile("cp.async.wait_group 0;" ::: "memory"); }
        } else {
            const uint32_t pB = pb + (uint32_t)(s & 1) * 4096;
            const uint32_t bB = bb + (uint32_t)(s & 3) * 8192;
#pragma unroll
            for (int ss = 0; ss < 2; ss++) {
                uint32_t a0[4], a1[4], a2[4], a3[4];
                ldm4(a0, pB + offA[0][ss]);
                ldm4(a1, pB + offA[1][ss]);
                ldm4(a2, pB + offA[2][ss]);
                ldm4(a3, pB + offA[3][ss]);
#pragma unroll
                for (int dg = 0; dg < 2; dg++) {
                    uint32_t q[4];
                    ldm4(q, bB + offB[dg][ss]);
                    mma_bf16(acc[0][dg * 2 + 0], a0, q[0], q[2]);
                    mma_bf16(acc[0][dg * 2 + 1], a0, q[1], q[3]);
                    mma_bf16(acc[1][dg * 2 + 0], a1, q[0], q[2]);
                    mma_bf16(acc[1][dg * 2 + 1], a1, q[1], q[3]);
                    mma_bf16(acc[2][dg * 2 + 0], a2, q[0], q[2]);
                    mma_bf16(acc[2][dg * 2 + 1], a2, q[1], q[3]);
                    mma_bf16(acc[3][dg * 2 + 0], a3, q[0], q[2]);
                    mma_bf16(acc[3][dg * 2 + 1], a3, q[1], q[3]);
                }
            }
        }
        __syncthreads();
    }

    // ---- epilogue: producers publish l; consumers normalize + residual
    if (warp < 4) {
        float lf = l0 + l1;
        lf += __shfl_xor_sync(0xffffffffu, lf, 1);
        if (jh == 0) sL[prow] = lf;
    }
    __syncthreads();
    if (warp >= 4) {
#pragma unroll
        for (int mt = 0; mt < 4; mt++) {
            const int rl = mt * 16 + (lane >> 2);
            const int rh = rl + 8;
            const float invl = 1.0f / sL[rl];
            const float invh = 1.0f / sL[rh];
            const size_t gl = ((size_t)b * NN + i0 + rl) * DD;
            const size_t gh = ((size_t)b * NN + i0 + rh) * DD;
#pragma unroll
            for (int n = 0; n < 4; n++) {
                const int col = cw * 32 + n * 8 + (lane & 3) * 2;
                float2 xa = *(const float2*)(Xin + gl + col);
                float2 xb = *(const float2*)(Xin + gh + col);
                float2 oa, ob;
                oa.x = xa.x + acc[mt][n][0] * invl;
                oa.y = xa.y + acc[mt][n][1] * invl;
                ob.x = xb.x + acc[mt][n][2] * invh;
                ob.y = xb.y + acc[mt][n][3] * invh;
                *(float2*)(Xout + gl + col) = oa;
                *(float2*)(Xout + gh + col) = ob;
            }
        }
    }
}

// ---------------- host launcher ----------------
extern "C" void kernel_launch(void* const* d_in, const int* in_sizes, int n_in,
                              void* d_out, int out_size)
{
    (void)in_sizes; (void)n_in; (void)out_size;
    const float* x   = (const float*)d_in[0];
    const int*   adj = (const int*)d_in[1];
    const float* Wg  = (const float*)d_in[2];
    const float* bg  = (const float*)d_in[3];
    const float* aa  = (const float*)d_in[4];
    float* out = (float*)d_out;

    float *xbuf, *s1, *s2;
    __nv_bfloat16 *hT;
    uint32_t *msk;
    cudaGetSymbolAddress((void**)&xbuf, g_x);
    cudaGetSymbolAddress((void**)&s1,   g_s1);
    cudaGetSymbolAddress((void**)&s2,   g_s2);
    cudaGetSymbolAddress((void**)&hT,   g_hT);
    cudaGetSymbolAddress((void**)&msk,  g_mask);

    const int smemH = 33792 + 16896;                      // 50688 B
    const int smemF = 8192 + 256 + 16640 + 8192 + 32768;  // 66048 B
    cudaFuncSetAttribute(k_h,     cudaFuncAttributeMaxDynamicSharedMemorySize, smemH);
    cudaFuncSetAttribute(k_fused, cudaFuncAttributeMaxDynamicSharedMemorySize, smemF);

    k_pack<<<dim3(NN / 8, BATCH), 256>>>(adj, msk);

    for (int l = 0; l < 3; l++) {
        const float* xin  = (l == 0) ? x : xbuf;
        float*       xout = (l == 2) ? out : xbuf;
        k_h<<<dim3(NN / 64, BATCH), 128, smemH>>>(
            xin, Wg + (size_t)l * DD * DD, bg + (size_t)l * DD,
            aa + (size_t)l * 2 * DD, aa + (size_t)l * 2 * DD + DD,
            hT, s1, s2);
        k_fused<<<dim3(NN / 64, BATCH), 256, smemF>>>(hT, msk, s1, s2, xin, xout);
    }
}

// round 13
// speedup vs baseline: 7.1345x; 1.0120x over previous
#include <cuda_runtime.h>
#include <cuda_bf16.h>
#include <cstdint>

#define BATCH 8
#define NN    2048
#define DD    128
#define LRELU_ALPHA 0.2f

// ---------------- device scratch (no allocation allowed) ----------------
__device__ __nv_bfloat16 g_hT[BATCH * DD * NN];   // transposed h, bf16 (B operand)
__device__ float g_x[BATCH * NN * DD];            // residual ping-pong
__device__ float g_s1[BATCH * NN];
__device__ float g_s2[BATCH * NN];
__device__ uint32_t g_mask[(size_t)BATCH * NN * (NN / 32)];   // adj bitmask, 4 MB

// ---------------- helpers ----------------
__device__ __forceinline__ uint32_t smem_u32(const void* p) {
    uint32_t a;
    asm("{ .reg .u64 t; cvta.to.shared.u64 t, %1; cvt.u32.u64 %0, t; }"
        : "=r"(a) : "l"(p));
    return a;
}
__device__ __forceinline__ void cpasync16(uint32_t dst, const void* src) {
    asm volatile("cp.async.cg.shared.global [%0], [%1], 16;"
                 :: "r"(dst), "l"(src) : "memory");
}
__device__ __forceinline__ void cp_commit() {
    asm volatile("cp.async.commit_group;" ::: "memory");
}
__device__ __forceinline__ void ldm4(uint32_t* r, uint32_t addr) {
    asm volatile("ldmatrix.sync.aligned.m8n8.x4.shared.b16 {%0,%1,%2,%3}, [%4];"
                 : "=r"(r[0]), "=r"(r[1]), "=r"(r[2]), "=r"(r[3]) : "r"(addr));
}
__device__ __forceinline__ void mma_bf16(float* c, const uint32_t* a,
                                         uint32_t b0, uint32_t b1) {
    asm volatile(
        "mma.sync.aligned.m16n8k16.row.col.f32.bf16.bf16.f32 "
        "{%0,%1,%2,%3}, {%4,%5,%6,%7}, {%8,%9}, {%0,%1,%2,%3};"
        : "+f"(c[0]), "+f"(c[1]), "+f"(c[2]), "+f"(c[3])
        : "r"(a[0]), "r"(a[1]), "r"(a[2]), "r"(a[3]), "r"(b0), "r"(b1));
}
__device__ __forceinline__ void mma_tf32(float* c, const uint32_t* a,
                                         uint32_t b0, uint32_t b1) {
    asm volatile(
        "mma.sync.aligned.m16n8k8.row.col.f32.tf32.tf32.f32 "
        "{%0,%1,%2,%3}, {%4,%5,%6,%7}, {%8,%9}, {%0,%1,%2,%3};"
        : "+f"(c[0]), "+f"(c[1]), "+f"(c[2]), "+f"(c[3])
        : "r"(a[0]), "r"(a[1]), "r"(a[2]), "r"(a[3]), "r"(b0), "r"(b1));
}
__device__ __forceinline__ uint32_t f2tf32(float v) {
    uint32_t r;
    asm("cvt.rna.tf32.f32 %0, %1;" : "=r"(r) : "f"(v));
    return r;
}
// swizzled byte offset of 16B chunk c (0..3) of row r in a [rows][32 bf16] tile
__device__ __forceinline__ uint32_t swz(int r, int c) {
    return (uint32_t)(r * 64 + (((c) ^ ((r >> 1) & 3)) << 4));
}
// pack two floats to bf16x2 {lo, hi}
__device__ __forceinline__ uint32_t pack_bf16x2(float lo, float hi) {
    uint32_t r;
    asm("cvt.rn.bf16x2.f32 %0, %1, %2;" : "=r"(r) : "f"(hi), "f"(lo));
    return r;
}

// ---------------- Kernel PK: pack adj into bitmask (runs ONCE) ----------------
__global__ __launch_bounds__(256) void k_pack(
    const int* __restrict__ ADJ, uint32_t* __restrict__ M)
{
    const int b    = blockIdx.y;
    const int row  = blockIdx.x * 8 + (threadIdx.x >> 5);
    const int lane = threadIdx.x & 31;
    const int* ar = ADJ + ((size_t)b * NN + row) * NN;
    uint32_t* mr  = M + ((size_t)b * NN + row) * (NN / 32);
#pragma unroll 4
    for (int w = 0; w < 16; w++) {
        int v0 = __ldg(ar + w * 128 +  0 + lane);
        int v1 = __ldg(ar + w * 128 + 32 + lane);
        int v2 = __ldg(ar + w * 128 + 64 + lane);
        int v3 = __ldg(ar + w * 128 + 96 + lane);
        uint32_t b0 = __ballot_sync(0xffffffffu, v0 != 0);
        uint32_t b1 = __ballot_sync(0xffffffffu, v1 != 0);
        uint32_t b2 = __ballot_sync(0xffffffffu, v2 != 0);
        uint32_t b3 = __ballot_sync(0xffffffffu, v3 != 0);
        if (lane == 0) *(uint4*)(mr + w * 4) = make_uint4(b0, b1, b2, b3);
    }
}

// ---------------- Kernel H: h = relu(x@W+b) via tf32 mma; HT bf16 + s1/s2 -------
// 256 threads, 8 warps: warp (wm, wn) owns 16 rows x 64 cols. K=128 in 4 chunks,
// W double-buffered through registers. dyn smem: sX [64][132] + sW [2][32][132]
// (sHT [128][66] bf16 reuses sW) = 67584 B.
__global__ __launch_bounds__(256) void k_h(
    const float* __restrict__ X, const float* __restrict__ W,
    const float* __restrict__ bias,
    const float* __restrict__ a1, const float* __restrict__ a2,
    __nv_bfloat16* __restrict__ HT,
    float* __restrict__ S1, float* __restrict__ S2)
{
    extern __shared__ char sm[];
    uint32_t* sX = (uint32_t*)sm;                       // [64][132]
    uint32_t* sW = (uint32_t*)(sm + 33792);             // [2][32][132]
    __nv_bfloat16* sHT = (__nv_bfloat16*)(sm + 33792);  // [128][66] (reuse)
    __shared__ float sS1p[2][64], sS2p[2][64];

    const int b   = blockIdx.y;
    const int i0  = blockIdx.x * 64;
    const int tid = threadIdx.x;
    const int warp = tid >> 5;
    const int lane = tid & 31;
    const int wm = warp >> 1;       // 0..3: m group (16 rows)
    const int wn = warp & 1;        // 0..1: n half (64 cols)

    // stage X tile (tf32) — 2048 float4, 8 per thread
    const float* Xb = X + ((size_t)b * NN + i0) * DD;
#pragma unroll
    for (int p = 0; p < 8; p++) {
        int gidx = p * 256 + tid;
        int row  = gidx >> 5;
        int c4   = (gidx & 31) << 2;
        float4 v = *(const float4*)(Xb + (size_t)row * DD + c4);
        *(uint4*)&sX[row * 132 + c4] =
            make_uint4(f2tf32(v.x), f2tf32(v.y), f2tf32(v.z), f2tf32(v.w));
    }
    // stage W chunk 0 — 1024 float4, 4 per thread
#pragma unroll
    for (int p = 0; p < 4; p++) {
        int gidx = p * 256 + tid;
        int r    = gidx >> 5;
        int c4   = (gidx & 31) << 2;
        float4 v = *(const float4*)(W + (size_t)r * DD + c4);
        *(uint4*)&sW[r * 132 + c4] =
            make_uint4(f2tf32(v.x), f2tf32(v.y), f2tf32(v.z), f2tf32(v.w));
    }
    __syncthreads();

    float acc[8][4];
#pragma unroll
    for (int nt = 0; nt < 8; nt++)
#pragma unroll
        for (int q = 0; q < 4; q++) acc[nt][q] = 0.f;

    const int rq = lane >> 2;
    const int kq = lane & 3;

    for (int kc = 0; kc < 4; kc++) {
        float4 wreg[4];
        if (kc < 3) {
#pragma unroll
            for (int p = 0; p < 4; p++) {
                int gidx = p * 256 + tid;
                int r    = gidx >> 5;
                int c4   = (gidx & 31) << 2;
                wreg[p] = *(const float4*)(W + (size_t)((kc + 1) * 32 + r) * DD + c4);
            }
        }
        const uint32_t* sWb = sW + (kc & 1) * 4224;
#pragma unroll
        for (int k8 = 0; k8 < 4; k8++) {
            const int kkA = kc * 32 + k8 * 8 + kq;
            const int r0  = wm * 16 + rq;
            uint32_t a[4];
            a[0] = sX[r0 * 132 + kkA];
            a[1] = sX[(r0 + 8) * 132 + kkA];
            a[2] = sX[r0 * 132 + kkA + 4];
            a[3] = sX[(r0 + 8) * 132 + kkA + 4];
            const int kwB = k8 * 8 + kq;
#pragma unroll
            for (int nt = 0; nt < 8; nt++) {
                const int n0 = wn * 64 + nt * 8 + rq;
                uint32_t b0 = sWb[kwB * 132 + n0];
                uint32_t b1 = sWb[(kwB + 4) * 132 + n0];
                mma_tf32(acc[nt], a, b0, b1);
            }
        }
        if (kc < 3) {
            uint32_t* sWn = sW + ((kc + 1) & 1) * 4224;
#pragma unroll
            for (int p = 0; p < 4; p++) {
                int gidx = p * 256 + tid;
                int r    = gidx >> 5;
                int c4   = (gidx & 31) << 2;
                *(uint4*)&sWn[r * 132 + c4] =
                    make_uint4(f2tf32(wreg[p].x), f2tf32(wreg[p].y),
                               f2tf32(wreg[p].z), f2tf32(wreg[p].w));
            }
        }
        __syncthreads();
    }

    // epilogue: bias+relu, partial s1/s2 dots over this warp's 64 cols, stage h^T
    const int rsm_lo = wm * 16 + rq;
    const int rsm_hi = rsm_lo + 8;
    float sum1_lo = 0.f, sum1_hi = 0.f, sum2_lo = 0.f, sum2_hi = 0.f;
#pragma unroll
    for (int nt = 0; nt < 8; nt++) {
        const int c = wn * 64 + nt * 8 + kq * 2;
        float bi0 = __ldg(bias + c), bi1 = __ldg(bias + c + 1);
        float h00 = fmaxf(acc[nt][0] + bi0, 0.f);
        float h01 = fmaxf(acc[nt][1] + bi1, 0.f);
        float h10 = fmaxf(acc[nt][2] + bi0, 0.f);
        float h11 = fmaxf(acc[nt][3] + bi1, 0.f);
        float2 A1 = *(const float2*)(a1 + c);
        float2 A2 = *(const float2*)(a2 + c);
        sum1_lo += h00 * A1.x + h01 * A1.y;
        sum1_hi += h10 * A1.x + h11 * A1.y;
        sum2_lo += h00 * A2.x + h01 * A2.y;
        sum2_hi += h10 * A2.x + h11 * A2.y;
        sHT[c * 66 + rsm_lo]       = __float2bfloat16(h00);
        sHT[(c + 1) * 66 + rsm_lo] = __float2bfloat16(h01);
        sHT[c * 66 + rsm_hi]       = __float2bfloat16(h10);
        sHT[(c + 1) * 66 + rsm_hi] = __float2bfloat16(h11);
    }
#pragma unroll
    for (int o = 1; o <= 2; o <<= 1) {
        sum1_lo += __shfl_xor_sync(0xffffffffu, sum1_lo, o);
        sum1_hi += __shfl_xor_sync(0xffffffffu, sum1_hi, o);
        sum2_lo += __shfl_xor_sync(0xffffffffu, sum2_lo, o);
        sum2_hi += __shfl_xor_sync(0xffffffffu, sum2_hi, o);
    }
    if (kq == 0) {
        sS1p[wn][rsm_lo] = sum1_lo;
        sS1p[wn][rsm_hi] = sum1_hi;
        sS2p[wn][rsm_lo] = sum2_lo;
        sS2p[wn][rsm_hi] = sum2_hi;
    }
    __syncthreads();
    if (tid < 64) {
        S1[(size_t)b * NN + i0 + tid] = sS1p[0][tid] + sS1p[1][tid];
        S2[(size_t)b * NN + i0 + tid] = sS2p[0][tid] + sS2p[1][tid];
    }

    // coalesced transposed writeout: thread pair = one d row (64B halves)
    const int drow = tid >> 1;
    const int half = tid & 1;
    const uint32_t sbase = smem_u32(sHT) + (uint32_t)(drow * 132 + half * 64);
    __nv_bfloat16* gdst = HT + ((size_t)b * DD + drow) * NN + i0 + half * 32;
#pragma unroll
    for (int g = 0; g < 4; g++) {
        uint32_t o0, o1, o2, o3;
        asm("ld.shared.b32 %0, [%1];" : "=r"(o0) : "r"(sbase + g * 16 + 0));
        asm("ld.shared.b32 %0, [%1];" : "=r"(o1) : "r"(sbase + g * 16 + 4));
        asm("ld.shared.b32 %0, [%1];" : "=r"(o2) : "r"(sbase + g * 16 + 8));
        asm("ld.shared.b32 %0, [%1];" : "=r"(o3) : "r"(sbase + g * 16 + 12));
        *(uint4*)((char*)gdst + g * 16) = make_uint4(o0, o1, o2, o3);
    }
}

// ---------------- Kernel F: producer/consumer fused softmax+aggregation ---------
// 64-j super-chunks (32 barrier iters). Warps 0-3 producers (exp/mask/pack + B
// cp.async 3-deep 16KB ring + row sums), warps 4-7 consumers (ldmatrix+HMMA,
// each owns 32 d-cols x 64 rows).
// dyn smem: s2s 8192 | sL 256 | msk 16640 | pbuf 2x8192 | Bbuf 3x16384 = 90624 B.
__global__ __launch_bounds__(256, 2) void k_fused(
    const __nv_bfloat16* __restrict__ HT, const uint32_t* __restrict__ MASK,
    const float* __restrict__ S1, const float* __restrict__ S2,
    const float* __restrict__ Xin, float* __restrict__ Xout)
{
    extern __shared__ char sm[];
    float*    s2s = (float*)sm;                       // [2048]
    float*    sL  = (float*)(sm + 8192);              // [64]
    uint32_t* msk = (uint32_t*)(sm + 8448);           // [64*65]
    const uint32_t pb = smem_u32(sm + 25088);         // 2 x 8192
    const uint32_t bb = smem_u32(sm + 41472);         // 3 x 16384
    __shared__ float s_red[8];

    const int b    = blockIdx.y;
    const int i0   = blockIdx.x * 64;
    const int tid  = threadIdx.x;
    const int warp = tid >> 5;
    const int lane = tid & 31;

    // ---- cooperative: s2 -> smem + global max; mask rows -> smem
    const float* s2g = S2 + (size_t)b * NN;
    float mx;
    {
        float4 v0 = *(const float4*)(s2g + tid * 8);
        float4 v1 = *(const float4*)(s2g + tid * 8 + 4);
        *(float4*)(s2s + tid * 8)     = v0;
        *(float4*)(s2s + tid * 8 + 4) = v1;
        mx = fmaxf(fmaxf(fmaxf(v0.x, v0.y), fmaxf(v0.z, v0.w)),
                   fmaxf(fmaxf(v1.x, v1.y), fmaxf(v1.z, v1.w)));
#pragma unroll
        for (int o = 16; o > 0; o >>= 1)
            mx = fmaxf(mx, __shfl_xor_sync(0xffffffffu, mx, o));
        if (lane == 0) s_red[warp] = mx;
    }
    {
        const uint32_t* mg = MASK + ((size_t)b * NN + i0) * 64;
#pragma unroll
        for (int k = 0; k < 16; k++) {
            int idx = tid + k * 256;
            int r = idx >> 6, w = idx & 63;
            msk[r * 65 + w] = mg[idx];
        }
    }
    __syncthreads();
    mx = fmaxf(fmaxf(fmaxf(s_red[0], s_red[1]), fmaxf(s_red[2], s_red[3])),
               fmaxf(fmaxf(s_red[4], s_red[5]), fmaxf(s_red[6], s_red[7])));

    const char* Hb = (const char*)(HT + (size_t)b * DD * NN);

    // ================= PRODUCER state =================
    const int prow = warp * 16 + (lane >> 1);   // producers: warps 0-3
    const int jh   = lane & 1;                  // j half (16 j)
    float s1r = 0.f, m = 0.f, l0 = 0.f, l1 = 0.f;
    if (warp < 4) {
        s1r = S1[(size_t)b * NN + i0 + prow];
        float t = s1r + mx;
        m = fmaxf(t, LRELU_ALPHA * t);
    }
    const uint32_t po0 = swz(prow, jh * 2);
    const uint32_t po1 = swz(prow, jh * 2 + 1);

    // compute p for 32-j chunk (2*s + c) into pbuf[s&1] tile c
    auto produce = [&](int s, int c) {
        const int kc = 2 * s + c;
        const uint32_t w = msk[prow * 65 + kc] >> (jh * 16);
        const float* sp = s2s + kc * 32 + jh * 16;
        float4 va = *(const float4*)(sp);
        float4 vb = *(const float4*)(sp + 4);
        float4 vc = *(const float4*)(sp + 8);
        float4 vd = *(const float4*)(sp + 12);
        float p[16];
        float z;
#define PCALC(i, val) \
        z = s1r + (val); z = fmaxf(z, LRELU_ALPHA * z); \
        z = __expf(z - m); p[i] = (w & (1u << (i))) ? z : 0.f;
        PCALC(0, va.x)  PCALC(1, va.y)  PCALC(2, va.z)  PCALC(3, va.w)
        PCALC(4, vb.x)  PCALC(5, vb.y)  PCALC(6, vb.z)  PCALC(7, vb.w)
        PCALC(8, vc.x)  PCALC(9, vc.y)  PCALC(10, vc.z) PCALC(11, vc.w)
        PCALC(12, vd.x) PCALC(13, vd.y) PCALC(14, vd.z) PCALC(15, vd.w)
#undef PCALC
        l0 += ((p[0] + p[1]) + (p[2] + p[3])) + ((p[4] + p[5]) + (p[6] + p[7]));
        l1 += ((p[8] + p[9]) + (p[10] + p[11])) + ((p[12] + p[13]) + (p[14] + p[15]));
        uint32_t r0 = pack_bf16x2(p[0], p[1]),  r1 = pack_bf16x2(p[2], p[3]);
        uint32_t r2 = pack_bf16x2(p[4], p[5]),  r3 = pack_bf16x2(p[6], p[7]);
        uint32_t r4 = pack_bf16x2(p[8], p[9]),  r5 = pack_bf16x2(p[10], p[11]);
        uint32_t r6 = pack_bf16x2(p[12], p[13]), r7 = pack_bf16x2(p[14], p[15]);
        const uint32_t tb = pb + (uint32_t)((s & 1) * 2 + c) * 4096;
        asm volatile("st.shared.v4.b32 [%0], {%1,%2,%3,%4};"
                     :: "r"(tb + po0), "r"(r0), "r"(r1), "r"(r2), "r"(r3));
        asm volatile("st.shared.v4.b32 [%0], {%1,%2,%3,%4};"
                     :: "r"(tb + po1), "r"(r4), "r"(r5), "r"(r6), "r"(r7));
    };
    // issue cp.async for B super-chunk ch (64 j = two 8KB tiles); 8x16B per thread
    auto loadB = [&](int ch) {
        const uint32_t dst = bb + (uint32_t)(ch % 3) * 16384;
        const char* src = Hb + (size_t)ch * 128;
#pragma unroll
        for (int q = 0; q < 8; q++) {
            const int ct  = q >> 2;
            const int idx = tid + (q & 3) * 128;
            const int r = idx >> 2, cc = idx & 3;
            cpasync16(dst + ct * 8192 + swz(r, cc),
                      src + (size_t)r * (NN * 2) + ct * 64 + cc * 16);
        }
        cp_commit();
    };

    // ================= CONSUMER state =================
    const int cw = warp - 4;                    // consumers: warps 4-7, 32 d-cols
    const int lr = lane & 15;
    const int lc = lane >> 4;
    uint32_t offA[4][2], offB[2][2];
#pragma unroll
    for (int mt = 0; mt < 4; mt++)
#pragma unroll
        for (int ss = 0; ss < 2; ss++)
            offA[mt][ss] = swz(mt * 16 + lr, 2 * ss + lc);
#pragma unroll
    for (int dg = 0; dg < 2; dg++)
#pragma unroll
        for (int ss = 0; ss < 2; ss++)
            offB[dg][ss] = swz(cw * 32 + dg * 16 + lr, 2 * ss + lc);

    float acc[4][4][4];
#pragma unroll
    for (int mt = 0; mt < 4; mt++)
#pragma unroll
        for (int n = 0; n < 4; n++)
#pragma unroll
            for (int q = 0; q < 4; q++) acc[mt][n][q] = 0.f;

    // ---- prologue
    if (warp < 4) {
        loadB(0); loadB(1);
        produce(0, 0); produce(0, 1);
        asm volatile("cp.async.wait_group 1;" ::: "memory");
    }
    __syncthreads();

    // ---- main loop: 32 super-chunks of 64 j
    for (int s = 0; s < 32; s++) {
        if (warp < 4) {
            if (s < 30) loadB(s + 2);
            if (s < 31) { produce(s + 1, 0); produce(s + 1, 1); }
            if (s < 30)      { asm volatile("cp.async.wait_group 1;" ::: "memory"); }
            else if (s == 30){ asm volatile("cp.async.wait_group 0;" ::: "memory"); }
        } else {
#pragma unroll
            for (int c = 0; c < 2; c++) {
                const uint32_t pt = pb + (uint32_t)((s & 1) * 2 + c) * 4096;
                const uint32_t bt = bb + (uint32_t)(s % 3) * 16384 + (uint32_t)c * 8192;
#pragma unroll
                for (int ss = 0; ss < 2; ss++) {
                    uint32_t a0[4], a1[4], a2[4], a3[4];
                    ldm4(a0, pt + offA[0][ss]);
                    ldm4(a1, pt + offA[1][ss]);
                    ldm4(a2, pt + offA[2][ss]);
                    ldm4(a3, pt + offA[3][ss]);
#pragma unroll
                    for (int dg = 0; dg < 2; dg++) {
                        uint32_t q[4];
                        ldm4(q, bt + offB[dg][ss]);
                        mma_bf16(acc[0][dg * 2 + 0], a0, q[0], q[2]);
                        mma_bf16(acc[0][dg * 2 + 1], a0, q[1], q[3]);
                        mma_bf16(acc[1][dg * 2 + 0], a1, q[0], q[2]);
                        mma_bf16(acc[1][dg * 2 + 1], a1, q[1], q[3]);
                        mma_bf16(acc[2][dg * 2 + 0], a2, q[0], q[2]);
                        mma_bf16(acc[2][dg * 2 + 1], a2, q[1], q[3]);
                        mma_bf16(acc[3][dg * 2 + 0], a3, q[0], q[2]);
                        mma_bf16(acc[3][dg * 2 + 1], a3, q[1], q[3]);
                    }
                }
            }
        }
        __syncthreads();
    }

    // ---- epilogue: producers publish l; consumers normalize + residual
    if (warp < 4) {
        float lf = l0 + l1;
        lf += __shfl_xor_sync(0xffffffffu, lf, 1);
        if (jh == 0) sL[prow] = lf;
    }
    __syncthreads();
    if (warp >= 4) {
#pragma unroll
        for (int mt = 0; mt < 4; mt++) {
            const int rl = mt * 16 + (lane >> 2);
            const int rh = rl + 8;
            const float invl = 1.0f / sL[rl];
            const float invh = 1.0f / sL[rh];
            const size_t gl = ((size_t)b * NN + i0 + rl) * DD;
            const size_t gh = ((size_t)b * NN + i0 + rh) * DD;
#pragma unroll
            for (int n = 0; n < 4; n++) {
                const int col = cw * 32 + n * 8 + (lane & 3) * 2;
                float2 xa = *(const float2*)(Xin + gl + col);
                float2 xb = *(const float2*)(Xin + gh + col);
                float2 oa, ob;
                oa.x = xa.x + acc[mt][n][0] * invl;
                oa.y = xa.y + acc[mt][n][1] * invl;
                ob.x = xb.x + acc[mt][n][2] * invh;
                ob.y = xb.y + acc[mt][n][3] * invh;
                *(float2*)(Xout + gl + col) = oa;
                *(float2*)(Xout + gh + col) = ob;
            }
        }
    }
}

// ---------------- host launcher ----------------
extern "C" void kernel_launch(void* const* d_in, const int* in_sizes, int n_in,
                              void* d_out, int out_size)
{
    (void)in_sizes; (void)n_in; (void)out_size;
    const float* x   = (const float*)d_in[0];
    const int*   adj = (const int*)d_in[1];
    const float* Wg  = (const float*)d_in[2];
    const float* bg  = (const float*)d_in[3];
    const float* aa  = (const float*)d_in[4];
    float* out = (float*)d_out;

    float *xbuf, *s1, *s2;
    __nv_bfloat16 *hT;
    uint32_t *msk;
    cudaGetSymbolAddress((void**)&xbuf, g_x);
    cudaGetSymbolAddress((void**)&s1,   g_s1);
    cudaGetSymbolAddress((void**)&s2,   g_s2);
    cudaGetSymbolAddress((void**)&hT,   g_hT);
    cudaGetSymbolAddress((void**)&msk,  g_mask);

    const int smemH = 33792 + 33792;                      // 67584 B
    const int smemF = 8192 + 256 + 16640 + 16384 + 49152; // 90624 B
    cudaFuncSetAttribute(k_h,     cudaFuncAttributeMaxDynamicSharedMemorySize, smemH);
    cudaFuncSetAttribute(k_fused, cudaFuncAttributeMaxDynamicSharedMemorySize, smemF);

    k_pack<<<dim3(NN / 8, BATCH), 256>>>(adj, msk);

    for (int l = 0; l < 3; l++) {
        const float* xin  = (l == 0) ? x : xbuf;
        float*       xout = (l == 2) ? out : xbuf;
        k_h<<<dim3(NN / 64, BATCH), 256, smemH>>>(
            xin, Wg + (size_t)l * DD * DD, bg + (size_t)l * DD,
            aa + (size_t)l * 2 * DD, aa + (size_t)l * 2 * DD + DD,
            hT, s1, s2);
        k_fused<<<dim3(NN / 64, BATCH), 256, smemF>>>(hT, msk, s1, s2, xin, xout);
    }
}